// round 5
// baseline (speedup 1.0000x reference)
#include <cuda_runtime.h>
#include <cstdint>
#include <math.h>

#define B_ 32768
#define H_ 512

#define CTA_M 128
#define NTH 256
#define ROWB 80                      // 64B data + 16B pad
#define PLANE_B (128 * ROWB)         // 10240
#define STAGE_B (4 * PLANE_B)        // 40960: A_hi, A_lo, W_hi, W_lo
#define SMEM_DYN (2 * STAGE_B)       // 81920

typedef signed char s8;

// ---- static device scratch ----
__device__ int   g_cnt[2];
__device__ int   g_idx[2][B_];
__device__ float g_sa1[2][B_];       // layer1 per-row A scale
__device__ float g_s2[B_];           // layer2-right shared row scale (h|le)
__device__ float g_sw[4096];         // per interleaved weight row scale
__device__ __align__(16) s8 g_x1q_h[2][(size_t)B_ * 1536];
__device__ __align__(16) s8 g_x1q_l[2][(size_t)B_ * 1536];
__device__ __align__(16) s8 g_leq_h[(size_t)B_ * 512];
__device__ __align__(16) s8 g_leq_l[(size_t)B_ * 512];
__device__ __align__(16) s8 g_h1q_h[2][(size_t)B_ * 512];
__device__ __align__(16) s8 g_h1q_l[2][(size_t)B_ * 512];
#define WI_TOTAL 4718592             // (1536+1536+512+1024)*1024
__device__ __align__(16) s8 g_wq_h[WI_TOTAL];
__device__ __align__(16) s8 g_wq_l[WI_TOTAL];

__constant__ int c_jobK[4]  = {1536, 1536, 512, 1024};
__constant__ int c_wioff[4] = {0, 1572864, 3145728, 3670016};

// ---- PTX helpers (baseline ISA only) ----
__device__ __forceinline__ uint32_t smem_u32(const void* p) {
    uint32_t a;
    asm("{ .reg .u64 t; cvta.to.shared.u64 t, %1; cvt.u32.u64 %0, t; }" : "=r"(a) : "l"(p));
    return a;
}
#define CP_ASYNC16(d, s) asm volatile("cp.async.cg.shared.global [%0], [%1], 16;" :: "r"(d), "l"(s))
#define CP_COMMIT()      asm volatile("cp.async.commit_group;" ::: "memory")
#define CP_WAIT1()       asm volatile("cp.async.wait_group 1;" ::: "memory")
#define CP_WAIT0()       asm volatile("cp.async.wait_group 0;" ::: "memory")
#define LDSM_X4(r, addr) \
    asm volatile("ldmatrix.sync.aligned.m8n8.x4.shared.b16 {%0,%1,%2,%3}, [%4];" \
        : "=r"((r)[0]), "=r"((r)[1]), "=r"((r)[2]), "=r"((r)[3]) : "r"(addr))
#define MMA_S8(c, a, b) \
    asm volatile("mma.sync.aligned.m16n8k32.row.col.s32.s8.s8.s32 " \
        "{%0,%1,%2,%3}, {%4,%5,%6,%7}, {%8,%9}, {%0,%1,%2,%3};" \
        : "+r"((c)[0]), "+r"((c)[1]), "+r"((c)[2]), "+r"((c)[3]) \
        : "r"((a)[0]), "r"((a)[1]), "r"((a)[2]), "r"((a)[3]), "r"((b)[0]), "r"((b)[1]))

__device__ __forceinline__ void quant2(float q, s8& hi, s8& lo) {
    int qh = __float2int_rn(q);
    int ql = __float2int_rn(254.f * (q - (float)qh));
    hi = (s8)qh; lo = (s8)ql;
}

// ---- small kernels ----
__global__ void zero_cnt_kernel() { if (threadIdx.x < 2) g_cnt[threadIdx.x] = 0; }

__global__ void build_idx_kernel(const int* __restrict__ group,
                                 float* __restrict__ mask_out, int write_mask) {
    int i = blockIdx.x * blockDim.x + threadIdx.x;
    if (i >= B_) return;
    int g = group[i];
    if (write_mask) mask_out[i] = (g == 2) ? 1.0f : 0.0f;
    if (g == 0)      { int p = atomicAdd(&g_cnt[0], 1); g_idx[0][p] = i; }
    else if (g == 1) { int p = atomicAdd(&g_cnt[1], 1); g_idx[1][p] = i; }
}

__global__ void zero_out_kernel(float* __restrict__ out) {
    int t = blockIdx.x * blockDim.x + threadIdx.x;
    if (t < B_ * (H_ / 4))
        reinterpret_cast<float4*>(out)[t] = make_float4(0.f, 0.f, 0.f, 0.f);
}

// weight prepack: per interleaved transposed row (2n+p), two-level int8 quantize
__global__ void prepack_wq_kernel(const float* w0h, const float* w0g,
                                  const float* w1h, const float* w1g,
                                  const float* w2h, const float* w2g,
                                  const float* w3h, const float* w3g) {
    int ri = blockIdx.x;                 // 0..1023
    int j  = blockIdx.y;                 // job
    int K  = c_jobK[j];
    int n  = ri >> 1;
    int par = ri & 1;
    const float* W = (j == 0) ? (par ? w0g : w0h)
                   : (j == 1) ? (par ? w1g : w1h)
                   : (j == 2) ? (par ? w2g : w2h)
                              : (par ? w3g : w3h);
    int tid = threadIdx.x;
    __shared__ float red[NTH];
    float v[6];
    float mx = 0.f;
#pragma unroll
    for (int i = 0; i < 6; ++i) {
        int c = tid + i * NTH;
        v[i] = (c < K) ? W[(size_t)c * 512 + n] : 0.f;
        mx = fmaxf(mx, fabsf(v[i]));
    }
    red[tid] = mx; __syncthreads();
    for (int s = NTH / 2; s > 0; s >>= 1) {
        if (tid < s) red[tid] = fmaxf(red[tid], red[tid + s]);
        __syncthreads();
    }
    float wmax = fmaxf(red[0], 1e-20f);
    float inv = 127.f / wmax;
    size_t base = (size_t)c_wioff[j] + (size_t)ri * K;
#pragma unroll
    for (int i = 0; i < 6; ++i) {
        int c = tid + i * NTH;
        if (c < K) {
            s8 hi, lo; quant2(v[i] * inv, hi, lo);
            g_wq_h[base + c] = hi; g_wq_l[base + c] = lo;
        }
    }
    if (tid == 0) g_sw[j * 1024 + ri] = wmax / 127.f;
}

// gather + two-level int8 quantize of activations
__global__ void pack_x1_kernel(const float* __restrict__ nh, const float* __restrict__ nc,
                               const float* __restrict__ lab, const float* __restrict__ le) {
    int p  = blockIdx.x;
    int br = blockIdx.y;
    if (p >= g_cnt[br]) return;
    int src = g_idx[br][p];
    int tid = threadIdx.x;
    __shared__ float red[NTH];

    float v[6];
    float mx = 0.f;
#pragma unroll
    for (int i = 0; i < 6; ++i) {
        int c = tid + i * NTH;
        float x = (c < 512) ? nh[(size_t)src * 512 + c]
                : (c < 1024) ? nc[(size_t)src * 512 + (c - 512)]
                             : lab[(size_t)src * 512 + (c - 1024)];
        v[i] = x;
        mx = fmaxf(mx, fabsf(x));
    }
    red[tid] = mx; __syncthreads();
    for (int s = NTH / 2; s > 0; s >>= 1) {
        if (tid < s) red[tid] = fmaxf(red[tid], red[tid + s]);
        __syncthreads();
    }
    float amax = fmaxf(red[0], 1e-20f);
    __syncthreads();
    float inv = 127.f / amax;
    s8* xh = g_x1q_h[br];
    s8* xl = g_x1q_l[br];
#pragma unroll
    for (int i = 0; i < 6; ++i) {
        int c = tid + i * NTH;
        s8 hi, lo; quant2(v[i] * inv, hi, lo);
        xh[(size_t)p * 1536 + c] = hi;
        xl[(size_t)p * 1536 + c] = lo;
    }
    if (tid == 0) g_sa1[br][p] = amax / 127.f;

    if (br == 1) {
        float u[2];
        u[0] = le[(size_t)src * 512 + tid];
        u[1] = le[(size_t)src * 512 + tid + 256];
        red[tid] = fmaxf(fabsf(u[0]), fabsf(u[1]));
        __syncthreads();
        for (int s = NTH / 2; s > 0; s >>= 1) {
            if (tid < s) red[tid] = fmaxf(red[tid], red[tid + s]);
            __syncthreads();
        }
        float s2 = fmaxf(1.f, red[0]) / 127.f;
        float inv2 = 1.f / s2;
#pragma unroll
        for (int i = 0; i < 2; ++i) {
            int c = tid + i * NTH;
            s8 hi, lo; quant2(u[i] * inv2, hi, lo);
            g_leq_h[(size_t)p * 512 + c] = hi;
            g_leq_l[(size_t)p * 512 + c] = lo;
        }
        if (tid == 0) g_s2[p] = s2;
    }
}

// ---- stage loader: 4 planes of 128 rows x 64 bytes ----
__device__ __forceinline__ void load_stage(uint32_t stu, int job, int br, int m0,
                                           int bx, int k0, int K, int wioff, int tid) {
    const s8 *ahi, *alo;
    int astr, acol;
    if (job <= 1)      { ahi = g_x1q_h[br]; alo = g_x1q_l[br]; astr = 1536; acol = k0; }
    else if (job == 2) { ahi = g_h1q_h[0];  alo = g_h1q_l[0];  astr = 512;  acol = k0; }
    else {
        if (k0 < 512)  { ahi = g_h1q_h[1];  alo = g_h1q_l[1];  astr = 512;  acol = k0; }
        else           { ahi = g_leq_h;     alo = g_leq_l;     astr = 512;  acol = k0 - 512; }
    }
#pragma unroll
    for (int i = 0; i < 2; ++i) {
        int idx = tid + i * NTH;
        int row = idx >> 2;
        int q   = idx & 3;
        uint32_t d = stu + row * ROWB + q * 16;
        CP_ASYNC16(d,               ahi + (size_t)(m0 + row) * astr + acol + q * 16);
        CP_ASYNC16(d + PLANE_B,     alo + (size_t)(m0 + row) * astr + acol + q * 16);
        int grow = bx * 128 + row;
        CP_ASYNC16(d + 2 * PLANE_B, g_wq_h + wioff + (size_t)grow * K + k0 + q * 16);
        CP_ASYNC16(d + 3 * PLANE_B, g_wq_l + wioff + (size_t)grow * K + k0 + q * 16);
    }
    CP_COMMIT();
}

// ---- fused gated GEMM via mma.sync int8x3 (two-level quantization) ----
__global__ void __launch_bounds__(NTH, 1)
gate_gemm_mma(int base_job,
              const float* __restrict__ bh_a, const float* __restrict__ bg_a,
              const float* __restrict__ bh_b, const float* __restrict__ bg_b,
              float* __restrict__ out) {
    extern __shared__ char smem[];
    int job = base_job + (int)blockIdx.z;
    int br  = (job == 1 || job == 3) ? 1 : 0;
    int mcnt = g_cnt[br];
    int m0 = blockIdx.y * CTA_M;
    if (m0 >= mcnt) return;
    int bx = blockIdx.x;
    int K  = c_jobK[job];
    int wioff = c_wioff[job];
    int tid = threadIdx.x;
    uint32_t sb = smem_u32(smem);

    int a1[2][8][4], a2[2][8][4];      // hi*hi ; (lo*hi + hi*lo)
#pragma unroll
    for (int i = 0; i < 2; ++i)
#pragma unroll
        for (int j = 0; j < 8; ++j)
#pragma unroll
            for (int q = 0; q < 4; ++q) { a1[i][j][q] = 0; a2[i][j][q] = 0; }

    const int nchunks = K / 64;        // 64 int8 k per chunk
    load_stage(sb, job, br, m0, bx, 0, K, wioff, tid);

    int wid = tid >> 5, lane = tid & 31;
    int wm = (wid & 3) * 32;
    int wn = (wid >> 2) * 64;
    uint32_t a_off  = (uint32_t)(wm + (lane & 15)) * ROWB + ((lane >> 4) << 4);
    uint32_t b_rowl = (lane & 7);
    uint32_t b_pair = (lane >> 4);
    uint32_t b_kh   = ((lane >> 3) & 1) * 16;

    for (int c = 0; c < nchunks; ++c) {
        int stg = c & 1;
        __syncthreads();
        if (c + 1 < nchunks) {
            load_stage(sb + (stg ^ 1) * STAGE_B, job, br, m0, bx, (c + 1) * 64, K, wioff, tid);
            CP_WAIT1();
        } else {
            CP_WAIT0();
        }
        __syncthreads();
        uint32_t stu = sb + stg * STAGE_B;

#pragma unroll
        for (int s = 0; s < 2; ++s) {
            uint32_t ah[2][4], al[2][4];
#pragma unroll
            for (int tm = 0; tm < 2; ++tm) {
                uint32_t addr = stu + a_off + tm * 16 * ROWB + s * 32;
                LDSM_X4(ah[tm], addr);
                LDSM_X4(al[tm], addr + PLANE_B);
            }
            uint32_t bhf[8][2], blf[8][2];
#pragma unroll
            for (int tn = 0; tn < 8; tn += 2) {
                uint32_t row = wn + (tn + b_pair) * 8 + b_rowl;
                uint32_t addr = stu + 2 * PLANE_B + row * ROWB + s * 32 + b_kh;
                uint32_t r[4];
                LDSM_X4(r, addr);
                bhf[tn][0] = r[0]; bhf[tn][1] = r[1];
                bhf[tn + 1][0] = r[2]; bhf[tn + 1][1] = r[3];
                LDSM_X4(r, addr + PLANE_B);
                blf[tn][0] = r[0]; blf[tn][1] = r[1];
                blf[tn + 1][0] = r[2]; blf[tn + 1][1] = r[3];
            }
#pragma unroll
            for (int tm = 0; tm < 2; ++tm)
#pragma unroll
                for (int tn = 0; tn < 8; ++tn) MMA_S8(a1[tm][tn], ah[tm], bhf[tn]);
#pragma unroll
            for (int tm = 0; tm < 2; ++tm)
#pragma unroll
                for (int tn = 0; tn < 8; ++tn) MMA_S8(a2[tm][tn], al[tm], bhf[tn]);
#pragma unroll
            for (int tm = 0; tm < 2; ++tm)
#pragma unroll
                for (int tn = 0; tn < 8; ++tn) MMA_S8(a2[tm][tn], ah[tm], blf[tn]);
        }
    }

    // ---- epilogue: dequant + bias + tanh*sigmoid (+ requantize for layer 2) ----
    const float* bh_p = (blockIdx.z == 0) ? bh_a : bh_b;
    const float* bg_p = (blockIdx.z == 0) ? bg_a : bg_b;
    int n_base = bx * 64 + (wid >> 2) * 32 + (lane & 3);
    int m_base = m0 + wm + (lane >> 2);

    float sa_r[2][2], qs_r[2][2];
#pragma unroll
    for (int tm = 0; tm < 2; ++tm)
#pragma unroll
        for (int rr = 0; rr < 2; ++rr) {
            int m = m_base + tm * 16 + rr * 8;
            int mm = (m < mcnt) ? m : 0;
            sa_r[tm][rr] = (job < 2)  ? g_sa1[br][mm]
                         : (job == 2) ? (1.f / 127.f)
                                      : g_s2[mm];
            qs_r[tm][rr] = (job == 0) ? 127.f
                         : (job == 1) ? __fdividef(1.f, g_s2[mm])
                                      : 0.f;
        }

    s8* h1h = g_h1q_h[br];
    s8* h1l = g_h1q_l[br];

#pragma unroll
    for (int tn = 0; tn < 8; ++tn) {
        int n = n_base + tn * 4;
        float swh = __ldg(&g_sw[job * 1024 + 2 * n]);
        float swg = __ldg(&g_sw[job * 1024 + 2 * n + 1]);
        float bhv = __ldg(bh_p + n);
        float bgv = __ldg(bg_p + n);
#pragma unroll
        for (int tm = 0; tm < 2; ++tm)
#pragma unroll
            for (int rr = 0; rr < 2; ++rr) {
                int m = m_base + tm * 16 + rr * 8;
                if (m < mcnt) {
                    float sa = sa_r[tm][rr];
                    float d1 = (float)a1[tm][tn][rr * 2 + 0]
                             + (float)a2[tm][tn][rr * 2 + 0] * (1.f / 254.f);
                    float d2 = (float)a1[tm][tn][rr * 2 + 1]
                             + (float)a2[tm][tn][rr * 2 + 1] * (1.f / 254.f);
                    float x = d1 * sa * swh + bhv;
                    float y = d2 * sa * swg + bgv;
                    float r = tanhf(x) * (1.0f / (1.0f + __expf(-y)));
                    if (job < 2) {
                        s8 hi, lo; quant2(r * qs_r[tm][rr], hi, lo);
                        h1h[(size_t)m * 512 + n] = hi;
                        h1l[(size_t)m * 512 + n] = lo;
                    } else {
                        out[(size_t)g_idx[br][m] * 512 + n] = r;
                    }
                }
            }
    }
}

// ---- launch ----
extern "C" void kernel_launch(void* const* d_in, const int* in_sizes, int n_in,
                              void* d_out, int out_size) {
    const float* node_hidden     = (const float*)d_in[0];
    const float* node_context    = (const float*)d_in[1];
    const float* label_embedding = (const float*)d_in[2];
    const float* left_embedding  = (const float*)d_in[3];
    const int*   group           = (const int*)  d_in[4];
    const float* Wl1h = (const float*)d_in[5];
    const float* bl1h = (const float*)d_in[6];
    const float* Wl1g = (const float*)d_in[7];
    const float* bl1g = (const float*)d_in[8];
    const float* Wl2h = (const float*)d_in[9];
    const float* bl2h = (const float*)d_in[10];
    const float* Wl2g = (const float*)d_in[11];
    const float* bl2g = (const float*)d_in[12];
    const float* Wr1h = (const float*)d_in[13];
    const float* br1h = (const float*)d_in[14];
    const float* Wr1g = (const float*)d_in[15];
    const float* br1g = (const float*)d_in[16];
    const float* Wr2h = (const float*)d_in[17];
    const float* br2h = (const float*)d_in[18];
    const float* Wr2g = (const float*)d_in[19];
    const float* br2g = (const float*)d_in[20];
    (void)in_sizes; (void)n_in;

    float* out_children = (float*)d_out;
    float* out_mask     = (float*)d_out + (size_t)B_ * H_;
    int write_mask = (out_size >= (int)((size_t)B_ * H_ + B_)) ? 1 : 0;

    cudaFuncSetAttribute(gate_gemm_mma, cudaFuncAttributeMaxDynamicSharedMemorySize, SMEM_DYN);

    zero_cnt_kernel<<<1, 32>>>();
    build_idx_kernel<<<B_ / 256, 256>>>(group, out_mask, write_mask);
    prepack_wq_kernel<<<dim3(1024, 4), NTH>>>(Wl1h, Wl1g, Wr1h, Wr1g,
                                              Wl2h, Wl2g, Wr2h, Wr2g);
    pack_x1_kernel<<<dim3(B_, 2), NTH>>>(node_hidden, node_context,
                                         label_embedding, left_embedding);
    zero_out_kernel<<<(B_ * (H_ / 4) + 255) / 256, 256>>>(out_children);

    dim3 grid(H_ / 64, B_ / CTA_M, 2);
    gate_gemm_mma<<<grid, NTH, SMEM_DYN>>>(0, bl1h, bl1g, br1h, br1g, nullptr);
    gate_gemm_mma<<<grid, NTH, SMEM_DYN>>>(2, bl2h, bl2g, br2h, br2g, out_children);
}

// round 6
// speedup vs baseline: 2.9066x; 2.9066x over previous
#include <cuda_runtime.h>
#include <cuda_fp16.h>
#include <cstdint>
#include <math.h>

#define B_ 32768
#define H_ 512

#define CTA_M 128
#define NTH 256
#define ROWB 80                      // 64B data (32 halves) + 16B pad
#define PLANE_B (128 * ROWB)         // 10240
#define STAGE_B (3 * PLANE_B)        // 30720: A_hi, A_lo, W_hi
#define SMEM_DYN (2 * STAGE_B)       // 61440

// ---- static device scratch ----
__device__ int g_cnt[2];
__device__ int g_idx[2][B_];
__device__ __align__(16) __half g_x1_h[2][(size_t)B_ * 1536];
__device__ __align__(16) __half g_x1_l[2][(size_t)B_ * 1536];
__device__ __align__(16) __half g_le_h[(size_t)B_ * 512];
__device__ __align__(16) __half g_le_l[(size_t)B_ * 512];
__device__ __align__(16) __half g_h1_h[2][(size_t)B_ * 512];
__device__ __align__(16) __half g_h1_l[2][(size_t)B_ * 512];
#define WI_TOTAL 4718592             // (1536+1536+512+1024)*1024
__device__ __align__(16) __half g_w[WI_TOTAL];

__constant__ int c_jobK[4]  = {1536, 1536, 512, 1024};
__constant__ int c_wioff[4] = {0, 1572864, 3145728, 3670016};

// ---- PTX helpers (baseline ISA only; no arch-'a' features) ----
__device__ __forceinline__ uint32_t smem_u32(const void* p) {
    uint32_t a;
    asm("{ .reg .u64 t; cvta.to.shared.u64 t, %1; cvt.u32.u64 %0, t; }" : "=r"(a) : "l"(p));
    return a;
}
#define CP_ASYNC16(d, s) asm volatile("cp.async.cg.shared.global [%0], [%1], 16;" :: "r"(d), "l"(s))
#define CP_COMMIT()      asm volatile("cp.async.commit_group;" ::: "memory")
#define CP_WAIT1()       asm volatile("cp.async.wait_group 1;" ::: "memory")
#define CP_WAIT0()       asm volatile("cp.async.wait_group 0;" ::: "memory")
#define LDSM_X4(r, addr) \
    asm volatile("ldmatrix.sync.aligned.m8n8.x4.shared.b16 {%0,%1,%2,%3}, [%4];" \
        : "=r"((r)[0]), "=r"((r)[1]), "=r"((r)[2]), "=r"((r)[3]) : "r"(addr))
// main term: f16 inputs, f32 accumulators
#define MMA_F32ACC(c, a, b) \
    asm volatile("mma.sync.aligned.m16n8k16.row.col.f32.f16.f16.f32 " \
        "{%0,%1,%2,%3}, {%4,%5,%6,%7}, {%8,%9}, {%0,%1,%2,%3};" \
        : "+f"((c)[0]), "+f"((c)[1]), "+f"((c)[2]), "+f"((c)[3]) \
        : "r"((a)[0]), "r"((a)[1]), "r"((a)[2]), "r"((a)[3]), "r"((b)[0]), "r"((b)[1]))
// correction term: f16 accumulators (packed half2 x2)
#define MMA_F16ACC(c, a, b) \
    asm volatile("mma.sync.aligned.m16n8k16.row.col.f16.f16.f16.f16 " \
        "{%0,%1}, {%2,%3,%4,%5}, {%6,%7}, {%0,%1};" \
        : "+r"((c)[0]), "+r"((c)[1]) \
        : "r"((a)[0]), "r"((a)[1]), "r"((a)[2]), "r"((a)[3]), "r"((b)[0]), "r"((b)[1]))

__device__ __forceinline__ void split2(float v, __half& hi, __half& lo) {
    hi = __float2half_rn(v);
    lo = __float2half_rn(v - __half2float(hi));
}

// ---- small kernels ----
__global__ void zero_cnt_kernel() { if (threadIdx.x < 2) g_cnt[threadIdx.x] = 0; }

__global__ void build_idx_kernel(const int* __restrict__ group,
                                 float* __restrict__ mask_out, int write_mask) {
    int i = blockIdx.x * blockDim.x + threadIdx.x;
    if (i >= B_) return;
    int g = group[i];
    if (write_mask) mask_out[i] = (g == 2) ? 1.0f : 0.0f;
    if (g == 0)      { int p = atomicAdd(&g_cnt[0], 1); g_idx[0][p] = i; }
    else if (g == 1) { int p = atomicAdd(&g_cnt[1], 1); g_idx[1][p] = i; }
}

// zero only rows with group==2 (others are fully scattered by layer-2 epilogue)
__global__ void zero_g2_kernel(const int* __restrict__ group, float* __restrict__ out) {
    int row = blockIdx.x;
    if (group[row] != 2) return;
    float4 z = make_float4(0.f, 0.f, 0.f, 0.f);
    reinterpret_cast<float4*>(out + (size_t)row * H_)[threadIdx.x] = z;
}

// weight prepack: [K,512] Wh,Wg -> interleaved transposed rows [2n+p][K], fp16
__global__ void prepack_w_kernel(const float* w0h, const float* w0g,
                                 const float* w1h, const float* w1g,
                                 const float* w2h, const float* w2g,
                                 const float* w3h, const float* w3g) {
    int j = blockIdx.z;
    const float* Wh = (j == 0) ? w0h : (j == 1) ? w1h : (j == 2) ? w2h : w3h;
    const float* Wg = (j == 0) ? w0g : (j == 1) ? w1g : (j == 2) ? w2g : w3g;
    int K = c_jobK[j];
    int k0 = blockIdx.x * 32;
    if (k0 >= K) return;
    int n0 = blockIdx.y * 32;
    __shared__ float sh[32][33], sg[32][33];
    int tx = threadIdx.x, ty = threadIdx.y;
#pragma unroll
    for (int i = 0; i < 4; ++i) {
        sh[ty + 8 * i][tx] = Wh[(size_t)(k0 + ty + 8 * i) * 512 + n0 + tx];
        sg[ty + 8 * i][tx] = Wg[(size_t)(k0 + ty + 8 * i) * 512 + n0 + tx];
    }
    __syncthreads();
    size_t base = (size_t)c_wioff[j];
#pragma unroll
    for (int i = 0; i < 4; ++i) {
        int n = n0 + ty + 8 * i;
        int k = k0 + tx;
        g_w[base + (size_t)(2 * n) * K + k]     = __float2half_rn(sh[tx][ty + 8 * i]);
        g_w[base + (size_t)(2 * n + 1) * K + k] = __float2half_rn(sg[tx][ty + 8 * i]);
    }
}

// gather + fp16 hi/lo split of activations (no scales needed)
__global__ void pack_x1_kernel(const float* __restrict__ nh, const float* __restrict__ nc,
                               const float* __restrict__ lab, const float* __restrict__ le) {
    int p  = blockIdx.x;
    int br = blockIdx.y;
    if (p >= g_cnt[br]) return;
    int src = g_idx[br][p];
    int tid = threadIdx.x;               // 128 threads
    __half* xh = g_x1_h[br];
    __half* xl = g_x1_l[br];
#pragma unroll
    for (int i = 0; i < 3; ++i) {
        int c4 = tid + i * 128;          // float4 index 0..383
        const float* srcp = (c4 < 128) ? nh : (c4 < 256) ? nc : lab;
        int loc = (c4 & 127) * 4;
        float4 v = *reinterpret_cast<const float4*>(srcp + (size_t)src * 512 + loc);
        __half h[4], l[4];
        split2(v.x, h[0], l[0]); split2(v.y, h[1], l[1]);
        split2(v.z, h[2], l[2]); split2(v.w, h[3], l[3]);
        *reinterpret_cast<uint2*>(xh + (size_t)p * 1536 + c4 * 4) = *reinterpret_cast<uint2*>(h);
        *reinterpret_cast<uint2*>(xl + (size_t)p * 1536 + c4 * 4) = *reinterpret_cast<uint2*>(l);
    }
    if (br == 1) {
        int c4 = tid;                    // 0..127 covers 512 floats
        float4 v = *reinterpret_cast<const float4*>(le + (size_t)src * 512 + c4 * 4);
        __half h[4], l[4];
        split2(v.x, h[0], l[0]); split2(v.y, h[1], l[1]);
        split2(v.z, h[2], l[2]); split2(v.w, h[3], l[3]);
        *reinterpret_cast<uint2*>(g_le_h + (size_t)p * 512 + c4 * 4) = *reinterpret_cast<uint2*>(h);
        *reinterpret_cast<uint2*>(g_le_l + (size_t)p * 512 + c4 * 4) = *reinterpret_cast<uint2*>(l);
    }
}

// ---- stage loader: 3 planes of 128 rows x 64 bytes ----
__device__ __forceinline__ void load_stage(uint32_t stu, int job, int br, int m0,
                                           int bx, int k0, int K, int wioff, int tid) {
    const __half *ahi, *alo;
    int astr, acol;
    if (job <= 1)      { ahi = g_x1_h[br]; alo = g_x1_l[br]; astr = 1536; acol = k0; }
    else if (job == 2) { ahi = g_h1_h[0];  alo = g_h1_l[0];  astr = 512;  acol = k0; }
    else {
        if (k0 < 512)  { ahi = g_h1_h[1];  alo = g_h1_l[1];  astr = 512;  acol = k0; }
        else           { ahi = g_le_h;     alo = g_le_l;     astr = 512;  acol = k0 - 512; }
    }
#pragma unroll
    for (int i = 0; i < 2; ++i) {
        int idx = tid + i * NTH;           // 0..511
        int row = idx >> 2;                // 0..127
        int q   = idx & 3;                 // 16B chunk = 8 halves
        uint32_t d = stu + row * ROWB + q * 16;
        CP_ASYNC16(d,               ahi + (size_t)(m0 + row) * astr + acol + q * 8);
        CP_ASYNC16(d + PLANE_B,     alo + (size_t)(m0 + row) * astr + acol + q * 8);
        int grow = bx * 128 + row;
        CP_ASYNC16(d + 2 * PLANE_B, g_w + wioff + (size_t)grow * K + k0 + q * 8);
    }
    CP_COMMIT();
}

// ---- fused gated GEMM via mma.sync fp16x2 (f32-acc main + f16-acc correction) ----
__global__ void __launch_bounds__(NTH, 1)
gate_gemm_mma(int base_job,
              const float* __restrict__ bh_a, const float* __restrict__ bg_a,
              const float* __restrict__ bh_b, const float* __restrict__ bg_b,
              float* __restrict__ out) {
    extern __shared__ char smem[];
    int job = base_job + (int)blockIdx.z;
    int br  = (job == 1 || job == 3) ? 1 : 0;
    int mcnt = g_cnt[br];
    int m0 = blockIdx.y * CTA_M;
    if (m0 >= mcnt) return;
    int bx = blockIdx.x;
    int K  = c_jobK[job];
    int wioff = c_wioff[job];
    int tid = threadIdx.x;
    uint32_t sb = smem_u32(smem);

    float    acc[2][8][4];               // main: f32
    uint32_t cor[2][8][2];               // correction: packed f16x2
#pragma unroll
    for (int i = 0; i < 2; ++i)
#pragma unroll
        for (int j = 0; j < 8; ++j) {
#pragma unroll
            for (int q = 0; q < 4; ++q) acc[i][j][q] = 0.f;
            cor[i][j][0] = 0u; cor[i][j][1] = 0u;
        }

    const int nchunks = K / 32;          // 32 halves per chunk (64B rows)
    load_stage(sb, job, br, m0, bx, 0, K, wioff, tid);

    int wid = tid >> 5, lane = tid & 31;
    int wm = (wid & 3) * 32;
    int wn = (wid >> 2) * 64;
    uint32_t a_off  = (uint32_t)(wm + (lane & 15)) * ROWB + ((lane >> 4) << 4);
    uint32_t b_rowl = (lane & 7);
    uint32_t b_pair = (lane >> 4);
    uint32_t b_kh   = ((lane >> 3) & 1) * 16;

    for (int c = 0; c < nchunks; ++c) {
        int stg = c & 1;
        __syncthreads();                  // prior compute on stage stg^1 done
        if (c + 1 < nchunks) {
            load_stage(sb + (stg ^ 1) * STAGE_B, job, br, m0, bx, (c + 1) * 32, K, wioff, tid);
            CP_WAIT1();
        } else {
            CP_WAIT0();
        }
        __syncthreads();                  // stage c data visible to all warps
        uint32_t stu = sb + stg * STAGE_B;

#pragma unroll
        for (int s = 0; s < 2; ++s) {
            uint32_t ah[2][4], al[2][4];
#pragma unroll
            for (int tm = 0; tm < 2; ++tm) {
                uint32_t addr = stu + a_off + tm * 16 * ROWB + s * 32;
                LDSM_X4(ah[tm], addr);
                LDSM_X4(al[tm], addr + PLANE_B);
            }
            uint32_t bf[8][2];
#pragma unroll
            for (int tn = 0; tn < 8; tn += 2) {
                uint32_t row = wn + (tn + b_pair) * 8 + b_rowl;
                uint32_t addr = stu + 2 * PLANE_B + row * ROWB + s * 32 + b_kh;
                uint32_t r[4];
                LDSM_X4(r, addr);
                bf[tn][0] = r[0]; bf[tn][1] = r[1];
                bf[tn + 1][0] = r[2]; bf[tn + 1][1] = r[3];
            }
#pragma unroll
            for (int tm = 0; tm < 2; ++tm)
#pragma unroll
                for (int tn = 0; tn < 8; ++tn) MMA_F32ACC(acc[tm][tn], ah[tm], bf[tn]);
#pragma unroll
            for (int tm = 0; tm < 2; ++tm)
#pragma unroll
                for (int tn = 0; tn < 8; ++tn) MMA_F16ACC(cor[tm][tn], al[tm], bf[tn]);
        }
    }

    // ---- epilogue: merge main+corr, bias, tanh*sigmoid; layer1 re-splits to fp16 ----
    const float* bh_p = (blockIdx.z == 0) ? bh_a : bh_b;
    const float* bg_p = (blockIdx.z == 0) ? bg_a : bg_b;
    int n_base = bx * 64 + (wid >> 2) * 32 + (lane & 3);
    int m_base = m0 + wm + (lane >> 2);
    __half* h1h = g_h1_h[br];
    __half* h1l = g_h1_l[br];

#pragma unroll
    for (int tn = 0; tn < 8; ++tn) {
        int n = n_base + tn * 4;
        float bhv = __ldg(bh_p + n);
        float bgv = __ldg(bg_p + n);
#pragma unroll
        for (int tm = 0; tm < 2; ++tm)
#pragma unroll
            for (int rr = 0; rr < 2; ++rr) {
                int m = m_base + tm * 16 + rr * 8;
                if (m < mcnt) {
                    __half2 cv = *reinterpret_cast<__half2*>(&cor[tm][tn][rr]);
                    float x = acc[tm][tn][rr * 2 + 0] + __low2float(cv)  + bhv;
                    float y = acc[tm][tn][rr * 2 + 1] + __high2float(cv) + bgv;
                    float r = tanhf(x) * (1.0f / (1.0f + __expf(-y)));
                    if (job < 2) {
                        __half hi, lo;
                        split2(r, hi, lo);
                        h1h[(size_t)m * 512 + n] = hi;
                        h1l[(size_t)m * 512 + n] = lo;
                    } else {
                        out[(size_t)g_idx[br][m] * 512 + n] = r;
                    }
                }
            }
    }
}

// ---- launch ----
extern "C" void kernel_launch(void* const* d_in, const int* in_sizes, int n_in,
                              void* d_out, int out_size) {
    const float* node_hidden     = (const float*)d_in[0];
    const float* node_context    = (const float*)d_in[1];
    const float* label_embedding = (const float*)d_in[2];
    const float* left_embedding  = (const float*)d_in[3];
    const int*   group           = (const int*)  d_in[4];
    const float* Wl1h = (const float*)d_in[5];
    const float* bl1h = (const float*)d_in[6];
    const float* Wl1g = (const float*)d_in[7];
    const float* bl1g = (const float*)d_in[8];
    const float* Wl2h = (const float*)d_in[9];
    const float* bl2h = (const float*)d_in[10];
    const float* Wl2g = (const float*)d_in[11];
    const float* bl2g = (const float*)d_in[12];
    const float* Wr1h = (const float*)d_in[13];
    const float* br1h = (const float*)d_in[14];
    const float* Wr1g = (const float*)d_in[15];
    const float* br1g = (const float*)d_in[16];
    const float* Wr2h = (const float*)d_in[17];
    const float* br2h = (const float*)d_in[18];
    const float* Wr2g = (const float*)d_in[19];
    const float* br2g = (const float*)d_in[20];
    (void)in_sizes; (void)n_in;

    float* out_children = (float*)d_out;
    float* out_mask     = (float*)d_out + (size_t)B_ * H_;
    int write_mask = (out_size >= (int)((size_t)B_ * H_ + B_)) ? 1 : 0;

    cudaFuncSetAttribute(gate_gemm_mma, cudaFuncAttributeMaxDynamicSharedMemorySize, SMEM_DYN);

    zero_cnt_kernel<<<1, 32>>>();
    build_idx_kernel<<<B_ / 256, 256>>>(group, out_mask, write_mask);
    prepack_w_kernel<<<dim3(48, 16, 4), dim3(32, 8)>>>(Wl1h, Wl1g, Wr1h, Wr1g,
                                                       Wl2h, Wl2g, Wr2h, Wr2g);
    pack_x1_kernel<<<dim3(B_, 2), 128>>>(node_hidden, node_context,
                                         label_embedding, left_embedding);
    zero_g2_kernel<<<B_, 128>>>(group, out_children);

    dim3 grid(H_ / 64, B_ / CTA_M, 2);   // idle M-blocks exit early
    gate_gemm_mma<<<grid, NTH, SMEM_DYN>>>(0, bl1h, bl1g, br1h, br1g, nullptr);
    gate_gemm_mma<<<grid, NTH, SMEM_DYN>>>(2, bl2h, bl2g, br2h, br2g, out_children);
}

// round 7
// speedup vs baseline: 3.2223x; 1.1086x over previous
#include <cuda_runtime.h>
#include <cuda_fp16.h>
#include <cstdint>
#include <math.h>

#define B_ 32768
#define H_ 512

#define CTA_M 128
#define NTH 256
#define ROWB 80                      // 64B data (32 halves) + 16B pad
#define PLANE_B (128 * ROWB)         // 10240
#define STAGE_B (3 * PLANE_B)        // 30720: A_hi, A_lo, W
#define NSTAGE 3
#define SMEM_DYN (NSTAGE * STAGE_B)  // 92160

// ---- static device scratch ----
__device__ int g_cnt[2];
__device__ int g_idx[2][B_];
__device__ __align__(16) __half g_x1_h[2][(size_t)B_ * 1536];
__device__ __align__(16) __half g_x1_l[2][(size_t)B_ * 1536];
__device__ __align__(16) __half g_le_h[(size_t)B_ * 512];
__device__ __align__(16) __half g_h1_h[2][(size_t)B_ * 512];
#define WI_TOTAL 4718592             // (1536+1536+512+1024)*1024
__device__ __align__(16) __half g_w[WI_TOTAL];

__constant__ int c_jobK[4]  = {1536, 1536, 512, 1024};
__constant__ int c_wioff[4] = {0, 1572864, 3145728, 3670016};

// ---- PTX helpers (baseline ISA only; no arch-'a' features) ----
__device__ __forceinline__ uint32_t smem_u32(const void* p) {
    uint32_t a;
    asm("{ .reg .u64 t; cvta.to.shared.u64 t, %1; cvt.u32.u64 %0, t; }" : "=r"(a) : "l"(p));
    return a;
}
#define CP_ASYNC16(d, s) asm volatile("cp.async.cg.shared.global [%0], [%1], 16;" :: "r"(d), "l"(s))
#define CP_COMMIT()      asm volatile("cp.async.commit_group;" ::: "memory")
#define CP_WAIT2()       asm volatile("cp.async.wait_group 2;" ::: "memory")
#define CP_WAIT1()       asm volatile("cp.async.wait_group 1;" ::: "memory")
#define CP_WAIT0()       asm volatile("cp.async.wait_group 0;" ::: "memory")
#define LDSM_X4(r, addr) \
    asm volatile("ldmatrix.sync.aligned.m8n8.x4.shared.b16 {%0,%1,%2,%3}, [%4];" \
        : "=r"((r)[0]), "=r"((r)[1]), "=r"((r)[2]), "=r"((r)[3]) : "r"(addr))
#define MMA_F32ACC(c, a, b) \
    asm volatile("mma.sync.aligned.m16n8k16.row.col.f32.f16.f16.f32 " \
        "{%0,%1,%2,%3}, {%4,%5,%6,%7}, {%8,%9}, {%0,%1,%2,%3};" \
        : "+f"((c)[0]), "+f"((c)[1]), "+f"((c)[2]), "+f"((c)[3]) \
        : "r"((a)[0]), "r"((a)[1]), "r"((a)[2]), "r"((a)[3]), "r"((b)[0]), "r"((b)[1]))
#define MMA_F16ACC(c, a, b) \
    asm volatile("mma.sync.aligned.m16n8k16.row.col.f16.f16.f16.f16 " \
        "{%0,%1}, {%2,%3,%4,%5}, {%6,%7}, {%0,%1};" \
        : "+r"((c)[0]), "+r"((c)[1]) \
        : "r"((a)[0]), "r"((a)[1]), "r"((a)[2]), "r"((a)[3]), "r"((b)[0]), "r"((b)[1]))

__device__ __forceinline__ void split2(float v, __half& hi, __half& lo) {
    hi = __float2half_rn(v);
    lo = __float2half_rn(v - __half2float(hi));
}

// ---- small kernels ----
__global__ void zero_cnt_kernel() { if (threadIdx.x < 2) g_cnt[threadIdx.x] = 0; }

__global__ void build_idx_kernel(const int* __restrict__ group,
                                 float* __restrict__ mask_out, int write_mask) {
    int i = blockIdx.x * blockDim.x + threadIdx.x;
    if (i >= B_) return;
    int g = group[i];
    if (write_mask) mask_out[i] = (g == 2) ? 1.0f : 0.0f;
    if (g == 0)      { int p = atomicAdd(&g_cnt[0], 1); g_idx[0][p] = i; }
    else if (g == 1) { int p = atomicAdd(&g_cnt[1], 1); g_idx[1][p] = i; }
}

// zero only rows with group==2
__global__ void zero_g2_kernel(const int* __restrict__ group, float* __restrict__ out) {
    int row = blockIdx.x;
    if (group[row] != 2) return;
    float4 z = make_float4(0.f, 0.f, 0.f, 0.f);
    reinterpret_cast<float4*>(out + (size_t)row * H_)[threadIdx.x] = z;
}

// weight prepack: [K,512] Wh,Wg -> interleaved transposed rows [2n+p][K], fp16
__global__ void prepack_w_kernel(const float* w0h, const float* w0g,
                                 const float* w1h, const float* w1g,
                                 const float* w2h, const float* w2g,
                                 const float* w3h, const float* w3g) {
    int j = blockIdx.z;
    const float* Wh = (j == 0) ? w0h : (j == 1) ? w1h : (j == 2) ? w2h : w3h;
    const float* Wg = (j == 0) ? w0g : (j == 1) ? w1g : (j == 2) ? w2g : w3g;
    int K = c_jobK[j];
    int k0 = blockIdx.x * 32;
    if (k0 >= K) return;
    int n0 = blockIdx.y * 32;
    __shared__ float sh[32][33], sg[32][33];
    int tx = threadIdx.x, ty = threadIdx.y;
#pragma unroll
    for (int i = 0; i < 4; ++i) {
        sh[ty + 8 * i][tx] = Wh[(size_t)(k0 + ty + 8 * i) * 512 + n0 + tx];
        sg[ty + 8 * i][tx] = Wg[(size_t)(k0 + ty + 8 * i) * 512 + n0 + tx];
    }
    __syncthreads();
    size_t base = (size_t)c_wioff[j];
#pragma unroll
    for (int i = 0; i < 4; ++i) {
        int n = n0 + ty + 8 * i;
        int k = k0 + tx;
        g_w[base + (size_t)(2 * n) * K + k]     = __float2half_rn(sh[tx][ty + 8 * i]);
        g_w[base + (size_t)(2 * n + 1) * K + k] = __float2half_rn(sg[tx][ty + 8 * i]);
    }
}

// gather + fp16 hi/lo split of activations (le: hi only)
__global__ void pack_x1_kernel(const float* __restrict__ nh, const float* __restrict__ nc,
                               const float* __restrict__ lab, const float* __restrict__ le) {
    int p  = blockIdx.x;
    int br = blockIdx.y;
    if (p >= g_cnt[br]) return;
    int src = g_idx[br][p];
    int tid = threadIdx.x;               // 128 threads
    __half* xh = g_x1_h[br];
    __half* xl = g_x1_l[br];
#pragma unroll
    for (int i = 0; i < 3; ++i) {
        int c4 = tid + i * 128;
        const float* srcp = (c4 < 128) ? nh : (c4 < 256) ? nc : lab;
        int loc = (c4 & 127) * 4;
        float4 v = *reinterpret_cast<const float4*>(srcp + (size_t)src * 512 + loc);
        __half h[4], l[4];
        split2(v.x, h[0], l[0]); split2(v.y, h[1], l[1]);
        split2(v.z, h[2], l[2]); split2(v.w, h[3], l[3]);
        *reinterpret_cast<uint2*>(xh + (size_t)p * 1536 + c4 * 4) = *reinterpret_cast<uint2*>(h);
        *reinterpret_cast<uint2*>(xl + (size_t)p * 1536 + c4 * 4) = *reinterpret_cast<uint2*>(l);
    }
    if (br == 1) {
        int c4 = tid;
        float4 v = *reinterpret_cast<const float4*>(le + (size_t)src * 512 + c4 * 4);
        __half h[4];
        h[0] = __float2half_rn(v.x); h[1] = __float2half_rn(v.y);
        h[2] = __float2half_rn(v.z); h[3] = __float2half_rn(v.w);
        *reinterpret_cast<uint2*>(g_le_h + (size_t)p * 512 + c4 * 4) = *reinterpret_cast<uint2*>(h);
    }
}

// ---- stage loader: A_hi (+ A_lo for layer 1) + W ----
__device__ __forceinline__ void load_stage(uint32_t stu, int job, int br, int m0,
                                           int bx, int k0, int K, int wioff, int tid) {
    const __half *ahi, *alo = nullptr;
    int astr, acol;
    bool use_lo = (job < 2);
    if (job <= 1)      { ahi = g_x1_h[br]; alo = g_x1_l[br]; astr = 1536; acol = k0; }
    else if (job == 2) { ahi = g_h1_h[0];  astr = 512;  acol = k0; }
    else {
        if (k0 < 512)  { ahi = g_h1_h[1];  astr = 512;  acol = k0; }
        else           { ahi = g_le_h;     astr = 512;  acol = k0 - 512; }
    }
#pragma unroll
    for (int i = 0; i < 2; ++i) {
        int idx = tid + i * NTH;           // 0..511
        int row = idx >> 2;                // 0..127
        int q   = idx & 3;                 // 16B chunk = 8 halves
        uint32_t d = stu + row * ROWB + q * 16;
        CP_ASYNC16(d, ahi + (size_t)(m0 + row) * astr + acol + q * 8);
        if (use_lo)
            CP_ASYNC16(d + PLANE_B, alo + (size_t)(m0 + row) * astr + acol + q * 8);
        int grow = bx * 128 + row;
        CP_ASYNC16(d + 2 * PLANE_B, g_w + wioff + (size_t)grow * K + k0 + q * 8);
    }
    CP_COMMIT();
}

// ---- fused gated GEMM: fp16 main (f32 acc) + fp16 correction (f16 acc, layer1 only) ----
__global__ void __launch_bounds__(NTH, 1)
gate_gemm_mma(int base_job,
              const float* __restrict__ bh_a, const float* __restrict__ bg_a,
              const float* __restrict__ bh_b, const float* __restrict__ bg_b,
              float* __restrict__ out) {
    extern __shared__ char smem[];
    int job = base_job + (int)blockIdx.z;
    int br  = (job == 1 || job == 3) ? 1 : 0;
    int mcnt = g_cnt[br];
    int m0 = blockIdx.y * CTA_M;
    if (m0 >= mcnt) return;
    int bx = blockIdx.x;
    int K  = c_jobK[job];
    int wioff = c_wioff[job];
    int tid = threadIdx.x;
    uint32_t sb = smem_u32(smem);
    const bool cor_on = (job < 2);

    float    acc[2][8][4];
    uint32_t cor[2][8][2];
#pragma unroll
    for (int i = 0; i < 2; ++i)
#pragma unroll
        for (int j = 0; j < 8; ++j) {
#pragma unroll
            for (int q = 0; q < 4; ++q) acc[i][j][q] = 0.f;
            cor[i][j][0] = 0u; cor[i][j][1] = 0u;
        }

    const int nchunks = K / 32;          // 32 halves per chunk
    load_stage(sb, job, br, m0, bx, 0, K, wioff, tid);
    if (nchunks > 1) load_stage(sb + STAGE_B, job, br, m0, bx, 32, K, wioff, tid);

    int wid = tid >> 5, lane = tid & 31;
    int wm = (wid & 3) * 32;
    int wn = (wid >> 2) * 64;
    uint32_t a_off  = (uint32_t)(wm + (lane & 15)) * ROWB + ((lane >> 4) << 4);
    uint32_t b_rowl = (lane & 7);
    uint32_t b_pair = (lane >> 4);
    uint32_t b_kh   = ((lane >> 3) & 1) * 16;

    int stg = 0;
    for (int c = 0; c < nchunks; ++c) {
        if (c > 0) __syncthreads();       // stage being overwritten (c+2)%3 ≡ (c-1)%3 consumed
        if (c + 2 < nchunks) {
            int tgt = (stg + 2 >= NSTAGE) ? (stg + 2 - NSTAGE) : (stg + 2);
            load_stage(sb + tgt * STAGE_B, job, br, m0, bx, (c + 2) * 32, K, wioff, tid);
            CP_WAIT2();
        } else if (c + 1 < nchunks) {
            CP_WAIT1();
        } else {
            CP_WAIT0();
        }
        __syncthreads();                  // stage c visible to all warps
        uint32_t stu = sb + stg * STAGE_B;
        stg = (stg + 1 >= NSTAGE) ? 0 : (stg + 1);

#pragma unroll
        for (int s = 0; s < 2; ++s) {
            uint32_t ah[2][4], al[2][4];
#pragma unroll
            for (int tm = 0; tm < 2; ++tm) {
                uint32_t addr = stu + a_off + tm * 16 * ROWB + s * 32;
                LDSM_X4(ah[tm], addr);
                if (cor_on) LDSM_X4(al[tm], addr + PLANE_B);
            }
            uint32_t bf[8][2];
#pragma unroll
            for (int tn = 0; tn < 8; tn += 2) {
                uint32_t row = wn + (tn + b_pair) * 8 + b_rowl;
                uint32_t addr = stu + 2 * PLANE_B + row * ROWB + s * 32 + b_kh;
                uint32_t r[4];
                LDSM_X4(r, addr);
                bf[tn][0] = r[0]; bf[tn][1] = r[1];
                bf[tn + 1][0] = r[2]; bf[tn + 1][1] = r[3];
            }
#pragma unroll
            for (int tm = 0; tm < 2; ++tm)
#pragma unroll
                for (int tn = 0; tn < 8; ++tn) MMA_F32ACC(acc[tm][tn], ah[tm], bf[tn]);
            if (cor_on) {
#pragma unroll
                for (int tm = 0; tm < 2; ++tm)
#pragma unroll
                    for (int tn = 0; tn < 8; ++tn) MMA_F16ACC(cor[tm][tn], al[tm], bf[tn]);
            }
        }
    }

    // ---- epilogue ----
    const float* bh_p = (blockIdx.z == 0) ? bh_a : bh_b;
    const float* bg_p = (blockIdx.z == 0) ? bg_a : bg_b;
    int n_base = bx * 64 + (wid >> 2) * 32 + (lane & 3);
    int m_base = m0 + wm + (lane >> 2);
    __half* h1h = g_h1_h[br];

#pragma unroll
    for (int tn = 0; tn < 8; ++tn) {
        int n = n_base + tn * 4;
        float bhv = __ldg(bh_p + n);
        float bgv = __ldg(bg_p + n);
#pragma unroll
        for (int tm = 0; tm < 2; ++tm)
#pragma unroll
            for (int rr = 0; rr < 2; ++rr) {
                int m = m_base + tm * 16 + rr * 8;
                if (m < mcnt) {
                    __half2 cv = *reinterpret_cast<__half2*>(&cor[tm][tn][rr]);
                    float x = acc[tm][tn][rr * 2 + 0] + __low2float(cv)  + bhv;
                    float y = acc[tm][tn][rr * 2 + 1] + __high2float(cv) + bgv;
                    float r = tanhf(x) * (1.0f / (1.0f + __expf(-y)));
                    if (job < 2) {
                        h1h[(size_t)m * 512 + n] = __float2half_rn(r);
                    } else {
                        out[(size_t)g_idx[br][m] * 512 + n] = r;
                    }
                }
            }
    }
}

// ---- launch ----
extern "C" void kernel_launch(void* const* d_in, const int* in_sizes, int n_in,
                              void* d_out, int out_size) {
    const float* node_hidden     = (const float*)d_in[0];
    const float* node_context    = (const float*)d_in[1];
    const float* label_embedding = (const float*)d_in[2];
    const float* left_embedding  = (const float*)d_in[3];
    const int*   group           = (const int*)  d_in[4];
    const float* Wl1h = (const float*)d_in[5];
    const float* bl1h = (const float*)d_in[6];
    const float* Wl1g = (const float*)d_in[7];
    const float* bl1g = (const float*)d_in[8];
    const float* Wl2h = (const float*)d_in[9];
    const float* bl2h = (const float*)d_in[10];
    const float* Wl2g = (const float*)d_in[11];
    const float* bl2g = (const float*)d_in[12];
    const float* Wr1h = (const float*)d_in[13];
    const float* br1h = (const float*)d_in[14];
    const float* Wr1g = (const float*)d_in[15];
    const float* br1g = (const float*)d_in[16];
    const float* Wr2h = (const float*)d_in[17];
    const float* br2h = (const float*)d_in[18];
    const float* Wr2g = (const float*)d_in[19];
    const float* br2g = (const float*)d_in[20];
    (void)in_sizes; (void)n_in;

    float* out_children = (float*)d_out;
    float* out_mask     = (float*)d_out + (size_t)B_ * H_;
    int write_mask = (out_size >= (int)((size_t)B_ * H_ + B_)) ? 1 : 0;

    cudaFuncSetAttribute(gate_gemm_mma, cudaFuncAttributeMaxDynamicSharedMemorySize, SMEM_DYN);

    zero_cnt_kernel<<<1, 32>>>();
    build_idx_kernel<<<B_ / 256, 256>>>(group, out_mask, write_mask);
    prepack_w_kernel<<<dim3(48, 16, 4), dim3(32, 8)>>>(Wl1h, Wl1g, Wr1h, Wr1g,
                                                       Wl2h, Wl2g, Wr2h, Wr2g);
    pack_x1_kernel<<<dim3(B_, 2), 128>>>(node_hidden, node_context,
                                         label_embedding, left_embedding);
    zero_g2_kernel<<<B_, 128>>>(group, out_children);

    dim3 grid(H_ / 64, B_ / CTA_M, 2);   // idle M-blocks exit early
    gate_gemm_mma<<<grid, NTH, SMEM_DYN>>>(0, bl1h, bl1g, br1h, br1g, nullptr);
    gate_gemm_mma<<<grid, NTH, SMEM_DYN>>>(2, bl2h, bl2g, br2h, br2g, out_children);
}

// round 8
// speedup vs baseline: 5.7237x; 1.7763x over previous
#include <cuda_runtime.h>
#include <cuda_fp16.h>
#include <cstdint>
#include <math.h>

#define B_ 32768
#define H_ 512

#define CTA_M 128
#define NTH 256
#define ROWB 80                      // 64B data (32 halves) + 16B pad
#define PLANE_B (128 * ROWB)         // 10240
#define STAGE_B (2 * PLANE_B)        // 20480: A, W
#define NSTAGE 4
#define SMEM_DYN (NSTAGE * STAGE_B)  // 81920 -> 2 CTAs/SM

// ---- static device scratch ----
__device__ int g_cnt[2];
__device__ int g_idx[2][B_];
__device__ __align__(16) __half g_x1[2][(size_t)B_ * 1536];
__device__ __align__(16) __half g_le[(size_t)B_ * 512];
__device__ __align__(16) __half g_h1[2][(size_t)B_ * 512];
#define WI_TOTAL 4718592             // (1536+1536+512+1024)*1024
__device__ __align__(16) __half g_w[WI_TOTAL];

__constant__ int c_jobK[4]  = {1536, 1536, 512, 1024};
__constant__ int c_wioff[4] = {0, 1572864, 3145728, 3670016};

// ---- PTX helpers (baseline ISA only; no arch-'a' features) ----
__device__ __forceinline__ uint32_t smem_u32(const void* p) {
    uint32_t a;
    asm("{ .reg .u64 t; cvta.to.shared.u64 t, %1; cvt.u32.u64 %0, t; }" : "=r"(a) : "l"(p));
    return a;
}
#define CP_ASYNC16(d, s) asm volatile("cp.async.cg.shared.global [%0], [%1], 16;" :: "r"(d), "l"(s))
#define CP_COMMIT()      asm volatile("cp.async.commit_group;" ::: "memory")
#define CP_WAIT3()       asm volatile("cp.async.wait_group 3;" ::: "memory")
#define CP_WAIT2()       asm volatile("cp.async.wait_group 2;" ::: "memory")
#define CP_WAIT1()       asm volatile("cp.async.wait_group 1;" ::: "memory")
#define CP_WAIT0()       asm volatile("cp.async.wait_group 0;" ::: "memory")
#define LDSM_X4(r, addr) \
    asm volatile("ldmatrix.sync.aligned.m8n8.x4.shared.b16 {%0,%1,%2,%3}, [%4];" \
        : "=r"((r)[0]), "=r"((r)[1]), "=r"((r)[2]), "=r"((r)[3]) : "r"(addr))
#define MMA_F32ACC(c, a, b) \
    asm volatile("mma.sync.aligned.m16n8k16.row.col.f32.f16.f16.f32 " \
        "{%0,%1,%2,%3}, {%4,%5,%6,%7}, {%8,%9}, {%0,%1,%2,%3};" \
        : "+f"((c)[0]), "+f"((c)[1]), "+f"((c)[2]), "+f"((c)[3]) \
        : "r"((a)[0]), "r"((a)[1]), "r"((a)[2]), "r"((a)[3]), "r"((b)[0]), "r"((b)[1]))

// ---- small kernels ----
__global__ void zero_cnt_kernel() { if (threadIdx.x < 2) g_cnt[threadIdx.x] = 0; }

__global__ void build_idx_kernel(const int* __restrict__ group,
                                 float* __restrict__ mask_out, int write_mask) {
    int i = blockIdx.x * blockDim.x + threadIdx.x;
    if (i >= B_) return;
    int g = group[i];
    if (write_mask) mask_out[i] = (g == 2) ? 1.0f : 0.0f;
    if (g == 0)      { int p = atomicAdd(&g_cnt[0], 1); g_idx[0][p] = i; }
    else if (g == 1) { int p = atomicAdd(&g_cnt[1], 1); g_idx[1][p] = i; }
}

// zero only rows with group==2
__global__ void zero_g2_kernel(const int* __restrict__ group, float* __restrict__ out) {
    int row = blockIdx.x;
    if (group[row] != 2) return;
    float4 z = make_float4(0.f, 0.f, 0.f, 0.f);
    reinterpret_cast<float4*>(out + (size_t)row * H_)[threadIdx.x] = z;
}

// weight prepack: [K,512] Wh,Wg -> interleaved transposed rows [2n+p][K], fp16
__global__ void prepack_w_kernel(const float* w0h, const float* w0g,
                                 const float* w1h, const float* w1g,
                                 const float* w2h, const float* w2g,
                                 const float* w3h, const float* w3g) {
    int j = blockIdx.z;
    const float* Wh = (j == 0) ? w0h : (j == 1) ? w1h : (j == 2) ? w2h : w3h;
    const float* Wg = (j == 0) ? w0g : (j == 1) ? w1g : (j == 2) ? w2g : w3g;
    int K = c_jobK[j];
    int k0 = blockIdx.x * 32;
    if (k0 >= K) return;
    int n0 = blockIdx.y * 32;
    __shared__ float sh[32][33], sg[32][33];
    int tx = threadIdx.x, ty = threadIdx.y;
#pragma unroll
    for (int i = 0; i < 4; ++i) {
        sh[ty + 8 * i][tx] = Wh[(size_t)(k0 + ty + 8 * i) * 512 + n0 + tx];
        sg[ty + 8 * i][tx] = Wg[(size_t)(k0 + ty + 8 * i) * 512 + n0 + tx];
    }
    __syncthreads();
    size_t base = (size_t)c_wioff[j];
#pragma unroll
    for (int i = 0; i < 4; ++i) {
        int n = n0 + ty + 8 * i;
        int k = k0 + tx;
        g_w[base + (size_t)(2 * n) * K + k]     = __float2half_rn(sh[tx][ty + 8 * i]);
        g_w[base + (size_t)(2 * n + 1) * K + k] = __float2half_rn(sg[tx][ty + 8 * i]);
    }
}

// gather + fp16 convert of activations (single pass, no split)
__global__ void pack_x1_kernel(const float* __restrict__ nh, const float* __restrict__ nc,
                               const float* __restrict__ lab, const float* __restrict__ le) {
    int p  = blockIdx.x;
    int br = blockIdx.y;
    if (p >= g_cnt[br]) return;
    int src = g_idx[br][p];
    int tid = threadIdx.x;               // 128 threads
    __half* x = g_x1[br];
#pragma unroll
    for (int i = 0; i < 3; ++i) {
        int c4 = tid + i * 128;
        const float* srcp = (c4 < 128) ? nh : (c4 < 256) ? nc : lab;
        int loc = (c4 & 127) * 4;
        float4 v = *reinterpret_cast<const float4*>(srcp + (size_t)src * 512 + loc);
        __half h[4];
        h[0] = __float2half_rn(v.x); h[1] = __float2half_rn(v.y);
        h[2] = __float2half_rn(v.z); h[3] = __float2half_rn(v.w);
        *reinterpret_cast<uint2*>(x + (size_t)p * 1536 + c4 * 4) = *reinterpret_cast<uint2*>(h);
    }
    if (br == 1) {
        int c4 = tid;
        float4 v = *reinterpret_cast<const float4*>(le + (size_t)src * 512 + c4 * 4);
        __half h[4];
        h[0] = __float2half_rn(v.x); h[1] = __float2half_rn(v.y);
        h[2] = __float2half_rn(v.z); h[3] = __float2half_rn(v.w);
        *reinterpret_cast<uint2*>(g_le + (size_t)p * 512 + c4 * 4) = *reinterpret_cast<uint2*>(h);
    }
}

// ---- stage loader: A + W planes ----
__device__ __forceinline__ void load_stage(uint32_t stu, int job, int br, int m0,
                                           int bx, int k0, int K, int wioff, int tid) {
    const __half* a;
    int astr, acol;
    if (job <= 1)      { a = g_x1[br]; astr = 1536; acol = k0; }
    else if (job == 2) { a = g_h1[0];  astr = 512;  acol = k0; }
    else {
        if (k0 < 512)  { a = g_h1[1];  astr = 512;  acol = k0; }
        else           { a = g_le;     astr = 512;  acol = k0 - 512; }
    }
#pragma unroll
    for (int i = 0; i < 2; ++i) {
        int idx = tid + i * NTH;           // 0..511
        int row = idx >> 2;                // 0..127
        int q   = idx & 3;                 // 16B chunk = 8 halves
        uint32_t d = stu + row * ROWB + q * 16;
        CP_ASYNC16(d, a + (size_t)(m0 + row) * astr + acol + q * 8);
        int grow = bx * 128 + row;
        CP_ASYNC16(d + PLANE_B, g_w + wioff + (size_t)grow * K + k0 + q * 8);
    }
    CP_COMMIT();
}

// ---- fused gated GEMM: single-pass fp16, f32 accumulators ----
__global__ void __launch_bounds__(NTH, 2)
gate_gemm_mma(int base_job,
              const float* __restrict__ bh_a, const float* __restrict__ bg_a,
              const float* __restrict__ bh_b, const float* __restrict__ bg_b,
              float* __restrict__ out) {
    extern __shared__ char smem[];
    int job = base_job + (int)blockIdx.z;
    int br  = (job == 1 || job == 3) ? 1 : 0;
    int mcnt = g_cnt[br];
    int m0 = blockIdx.y * CTA_M;
    if (m0 >= mcnt) return;
    int bx = blockIdx.x;
    int K  = c_jobK[job];
    int wioff = c_wioff[job];
    int tid = threadIdx.x;
    uint32_t sb = smem_u32(smem);

    float acc[2][8][4];
#pragma unroll
    for (int i = 0; i < 2; ++i)
#pragma unroll
        for (int j = 0; j < 8; ++j)
#pragma unroll
            for (int q = 0; q < 4; ++q) acc[i][j][q] = 0.f;

    const int nchunks = K / 32;          // 32 halves per chunk
    load_stage(sb, job, br, m0, bx, 0, K, wioff, tid);
    if (nchunks > 1) load_stage(sb + STAGE_B, job, br, m0, bx, 32, K, wioff, tid);
    if (nchunks > 2) load_stage(sb + 2 * STAGE_B, job, br, m0, bx, 64, K, wioff, tid);

    int wid = tid >> 5, lane = tid & 31;
    int wm = (wid & 3) * 32;
    int wn = (wid >> 2) * 64;
    uint32_t a_off  = (uint32_t)(wm + (lane & 15)) * ROWB + ((lane >> 4) << 4);
    uint32_t b_rowl = (lane & 7);
    uint32_t b_pair = (lane >> 4);
    uint32_t b_kh   = ((lane >> 3) & 1) * 16;

    for (int c = 0; c < nchunks; ++c) {
        int slot = c & (NSTAGE - 1);
        if (c > 0) __syncthreads();       // slot (c+3)%4 ≡ (c-1)%4 fully consumed
        int rem = nchunks - c;            // groups in flight before new issue
        if (c + 3 < nchunks) {
            load_stage(sb + ((c + 3) & (NSTAGE - 1)) * STAGE_B,
                       job, br, m0, bx, (c + 3) * 32, K, wioff, tid);
            CP_WAIT3();
        } else if (rem == 3) {
            CP_WAIT2();
        } else if (rem == 2) {
            CP_WAIT1();
        } else {
            CP_WAIT0();
        }
        __syncthreads();                  // stage c visible to all warps
        uint32_t stu = sb + slot * STAGE_B;

#pragma unroll
        for (int s = 0; s < 2; ++s) {
            uint32_t ah[2][4];
#pragma unroll
            for (int tm = 0; tm < 2; ++tm)
                LDSM_X4(ah[tm], stu + a_off + tm * 16 * ROWB + s * 32);
            uint32_t bf[8][2];
#pragma unroll
            for (int tn = 0; tn < 8; tn += 2) {
                uint32_t row = wn + (tn + b_pair) * 8 + b_rowl;
                uint32_t addr = stu + PLANE_B + row * ROWB + s * 32 + b_kh;
                uint32_t r[4];
                LDSM_X4(r, addr);
                bf[tn][0] = r[0]; bf[tn][1] = r[1];
                bf[tn + 1][0] = r[2]; bf[tn + 1][1] = r[3];
            }
#pragma unroll
            for (int tm = 0; tm < 2; ++tm)
#pragma unroll
                for (int tn = 0; tn < 8; ++tn) MMA_F32ACC(acc[tm][tn], ah[tm], bf[tn]);
        }
    }

    // ---- epilogue: bias + tanh*sigmoid; layer1 -> fp16 h1; layer2 -> scatter fp32 ----
    const float* bh_p = (blockIdx.z == 0) ? bh_a : bh_b;
    const float* bg_p = (blockIdx.z == 0) ? bg_a : bg_b;
    int n_base = bx * 64 + (wid >> 2) * 32 + (lane & 3);
    int m_base = m0 + wm + (lane >> 2);
    __half* h1 = g_h1[br];

#pragma unroll
    for (int tn = 0; tn < 8; ++tn) {
        int n = n_base + tn * 4;
        float bhv = __ldg(bh_p + n);
        float bgv = __ldg(bg_p + n);
#pragma unroll
        for (int tm = 0; tm < 2; ++tm)
#pragma unroll
            for (int rr = 0; rr < 2; ++rr) {
                int m = m_base + tm * 16 + rr * 8;
                if (m < mcnt) {
                    float x = acc[tm][tn][rr * 2 + 0] + bhv;
                    float y = acc[tm][tn][rr * 2 + 1] + bgv;
                    float r = tanhf(x) * (1.0f / (1.0f + __expf(-y)));
                    if (job < 2) {
                        h1[(size_t)m * 512 + n] = __float2half_rn(r);
                    } else {
                        out[(size_t)g_idx[br][m] * 512 + n] = r;
                    }
                }
            }
    }
}

// ---- launch ----
extern "C" void kernel_launch(void* const* d_in, const int* in_sizes, int n_in,
                              void* d_out, int out_size) {
    const float* node_hidden     = (const float*)d_in[0];
    const float* node_context    = (const float*)d_in[1];
    const float* label_embedding = (const float*)d_in[2];
    const float* left_embedding  = (const float*)d_in[3];
    const int*   group           = (const int*)  d_in[4];
    const float* Wl1h = (const float*)d_in[5];
    const float* bl1h = (const float*)d_in[6];
    const float* Wl1g = (const float*)d_in[7];
    const float* bl1g = (const float*)d_in[8];
    const float* Wl2h = (const float*)d_in[9];
    const float* bl2h = (const float*)d_in[10];
    const float* Wl2g = (const float*)d_in[11];
    const float* bl2g = (const float*)d_in[12];
    const float* Wr1h = (const float*)d_in[13];
    const float* br1h = (const float*)d_in[14];
    const float* Wr1g = (const float*)d_in[15];
    const float* br1g = (const float*)d_in[16];
    const float* Wr2h = (const float*)d_in[17];
    const float* br2h = (const float*)d_in[18];
    const float* Wr2g = (const float*)d_in[19];
    const float* br2g = (const float*)d_in[20];
    (void)in_sizes; (void)n_in;

    float* out_children = (float*)d_out;
    float* out_mask     = (float*)d_out + (size_t)B_ * H_;
    int write_mask = (out_size >= (int)((size_t)B_ * H_ + B_)) ? 1 : 0;

    cudaFuncSetAttribute(gate_gemm_mma, cudaFuncAttributeMaxDynamicSharedMemorySize, SMEM_DYN);

    zero_cnt_kernel<<<1, 32>>>();
    build_idx_kernel<<<B_ / 256, 256>>>(group, out_mask, write_mask);
    prepack_w_kernel<<<dim3(48, 16, 4), dim3(32, 8)>>>(Wl1h, Wl1g, Wr1h, Wr1g,
                                                       Wl2h, Wl2g, Wr2h, Wr2g);
    pack_x1_kernel<<<dim3(B_, 2), 128>>>(node_hidden, node_context,
                                         label_embedding, left_embedding);
    zero_g2_kernel<<<B_, 128>>>(group, out_children);

    dim3 grid(H_ / 64, B_ / CTA_M, 2);   // idle M-blocks exit early
    gate_gemm_mma<<<grid, NTH, SMEM_DYN>>>(0, bl1h, bl1g, br1h, br1g, nullptr);
    gate_gemm_mma<<<grid, NTH, SMEM_DYN>>>(2, bl2h, bl2g, br2h, br2g, out_children);
}

// round 9
// speedup vs baseline: 6.1192x; 1.0691x over previous
#include <cuda_runtime.h>
#include <cuda_fp16.h>
#include <cstdint>
#include <math.h>

#define B_ 32768
#define H_ 512

#define CTA_M 128
#define NTH 256
#define ROWB 80                      // 64B data (32 halves) + 16B pad
#define PLANE_B (128 * ROWB)         // 10240
#define STAGE_B (2 * PLANE_B)        // 20480: A, W
#define NSTAGE 4
#define SMEM_DYN (NSTAGE * STAGE_B)  // 81920 -> 2 CTAs/SM

// ---- static device scratch ----
__device__ int g_cnt[2];
__device__ int g_idx[2][B_];
__device__ __align__(16) __half g_x1[2][(size_t)B_ * 1536];
__device__ __align__(16) __half g_le[(size_t)B_ * 512];
__device__ __align__(16) __half g_h1[2][(size_t)B_ * 512];
#define WI_TOTAL 4718592             // (1536+1536+512+1024)*1024
__device__ __align__(16) __half g_w[WI_TOTAL];

__constant__ int c_jobK[4]  = {1536, 1536, 512, 1024};
__constant__ int c_wioff[4] = {0, 1572864, 3145728, 3670016};

// ---- PTX helpers (baseline ISA only; no arch-'a' features) ----
__device__ __forceinline__ uint32_t smem_u32(const void* p) {
    uint32_t a;
    asm("{ .reg .u64 t; cvta.to.shared.u64 t, %1; cvt.u32.u64 %0, t; }" : "=r"(a) : "l"(p));
    return a;
}
#define CP_ASYNC16(d, s) asm volatile("cp.async.cg.shared.global [%0], [%1], 16;" :: "r"(d), "l"(s))
#define CP_COMMIT()      asm volatile("cp.async.commit_group;" ::: "memory")
#define CP_WAIT3()       asm volatile("cp.async.wait_group 3;" ::: "memory")
#define CP_WAIT2()       asm volatile("cp.async.wait_group 2;" ::: "memory")
#define CP_WAIT1()       asm volatile("cp.async.wait_group 1;" ::: "memory")
#define CP_WAIT0()       asm volatile("cp.async.wait_group 0;" ::: "memory")
#define LDSM_X4(r, addr) \
    asm volatile("ldmatrix.sync.aligned.m8n8.x4.shared.b16 {%0,%1,%2,%3}, [%4];" \
        : "=r"((r)[0]), "=r"((r)[1]), "=r"((r)[2]), "=r"((r)[3]) : "r"(addr))
#define MMA_F32ACC(c, a, b) \
    asm volatile("mma.sync.aligned.m16n8k16.row.col.f32.f16.f16.f32 " \
        "{%0,%1,%2,%3}, {%4,%5,%6,%7}, {%8,%9}, {%0,%1,%2,%3};" \
        : "+f"((c)[0]), "+f"((c)[1]), "+f"((c)[2]), "+f"((c)[3]) \
        : "r"((a)[0]), "r"((a)[1]), "r"((a)[2]), "r"((a)[3]), "r"((b)[0]), "r"((b)[1]))

// ---- small kernels ----
__global__ void zero_cnt_kernel() { if (threadIdx.x < 2) g_cnt[threadIdx.x] = 0; }

// fused prep: classify row, build compact index, gather+convert activations,
// zero g==2 output rows, write mask. One block per source row.
__global__ void prep_kernel(const float* __restrict__ nh, const float* __restrict__ nc,
                            const float* __restrict__ lab, const float* __restrict__ le,
                            const int* __restrict__ group,
                            float* __restrict__ out_children,
                            float* __restrict__ mask_out, int write_mask) {
    int row = blockIdx.x;
    int tid = threadIdx.x;               // 128 threads
    int g = __ldg(group + row);
    __shared__ int s_p;
    if (tid == 0) {
        if (write_mask) mask_out[row] = (g == 2) ? 1.0f : 0.0f;
        if (g < 2) {
            int p = atomicAdd(&g_cnt[g], 1);
            g_idx[g][p] = row;
            s_p = p;
        }
    }
    __syncthreads();
    if (g == 2) {
        // finished row: output is zeros
        float4 z = make_float4(0.f, 0.f, 0.f, 0.f);
        reinterpret_cast<float4*>(out_children + (size_t)row * H_)[tid] = z;
        return;
    }
    int p = s_p;
    __half* x = g_x1[g];
#pragma unroll
    for (int i = 0; i < 3; ++i) {
        int c4 = tid + i * 128;
        const float* srcp = (c4 < 128) ? nh : (c4 < 256) ? nc : lab;
        int loc = (c4 & 127) * 4;
        float4 v = *reinterpret_cast<const float4*>(srcp + (size_t)row * 512 + loc);
        __half h[4];
        h[0] = __float2half_rn(v.x); h[1] = __float2half_rn(v.y);
        h[2] = __float2half_rn(v.z); h[3] = __float2half_rn(v.w);
        *reinterpret_cast<uint2*>(x + (size_t)p * 1536 + c4 * 4) = *reinterpret_cast<uint2*>(h);
    }
    if (g == 1) {
        float4 v = *reinterpret_cast<const float4*>(le + (size_t)row * 512 + tid * 4);
        __half h[4];
        h[0] = __float2half_rn(v.x); h[1] = __float2half_rn(v.y);
        h[2] = __float2half_rn(v.z); h[3] = __float2half_rn(v.w);
        *reinterpret_cast<uint2*>(g_le + (size_t)p * 512 + tid * 4) = *reinterpret_cast<uint2*>(h);
    }
}

// weight prepack: [K,512] Wh,Wg -> interleaved transposed rows [2n+p][K], fp16
__global__ void prepack_w_kernel(const float* w0h, const float* w0g,
                                 const float* w1h, const float* w1g,
                                 const float* w2h, const float* w2g,
                                 const float* w3h, const float* w3g) {
    int j = blockIdx.z;
    const float* Wh = (j == 0) ? w0h : (j == 1) ? w1h : (j == 2) ? w2h : w3h;
    const float* Wg = (j == 0) ? w0g : (j == 1) ? w1g : (j == 2) ? w2g : w3g;
    int K = c_jobK[j];
    int k0 = blockIdx.x * 32;
    if (k0 >= K) return;
    int n0 = blockIdx.y * 32;
    __shared__ float sh[32][33], sg[32][33];
    int tx = threadIdx.x, ty = threadIdx.y;
#pragma unroll
    for (int i = 0; i < 4; ++i) {
        sh[ty + 8 * i][tx] = Wh[(size_t)(k0 + ty + 8 * i) * 512 + n0 + tx];
        sg[ty + 8 * i][tx] = Wg[(size_t)(k0 + ty + 8 * i) * 512 + n0 + tx];
    }
    __syncthreads();
    size_t base = (size_t)c_wioff[j];
#pragma unroll
    for (int i = 0; i < 4; ++i) {
        int n = n0 + ty + 8 * i;
        int k = k0 + tx;
        g_w[base + (size_t)(2 * n) * K + k]     = __float2half_rn(sh[tx][ty + 8 * i]);
        g_w[base + (size_t)(2 * n + 1) * K + k] = __float2half_rn(sg[tx][ty + 8 * i]);
    }
}

// ---- stage loader: A + W planes ----
__device__ __forceinline__ void load_stage(uint32_t stu, int job, int br, int m0,
                                           int bx, int k0, int K, int wioff, int tid) {
    const __half* a;
    int astr, acol;
    if (job <= 1)      { a = g_x1[br]; astr = 1536; acol = k0; }
    else if (job == 2) { a = g_h1[0];  astr = 512;  acol = k0; }
    else {
        if (k0 < 512)  { a = g_h1[1];  astr = 512;  acol = k0; }
        else           { a = g_le;     astr = 512;  acol = k0 - 512; }
    }
#pragma unroll
    for (int i = 0; i < 2; ++i) {
        int idx = tid + i * NTH;           // 0..511
        int row = idx >> 2;                // 0..127
        int q   = idx & 3;                 // 16B chunk = 8 halves
        uint32_t d = stu + row * ROWB + q * 16;
        CP_ASYNC16(d, a + (size_t)(m0 + row) * astr + acol + q * 8);
        int grow = bx * 128 + row;
        CP_ASYNC16(d + PLANE_B, g_w + wioff + (size_t)grow * K + k0 + q * 8);
    }
    CP_COMMIT();
}

// ---- fused gated GEMM: single-pass fp16, f32 accumulators ----
__global__ void __launch_bounds__(NTH, 2)
gate_gemm_mma(int base_job,
              const float* __restrict__ bh_a, const float* __restrict__ bg_a,
              const float* __restrict__ bh_b, const float* __restrict__ bg_b,
              float* __restrict__ out) {
    extern __shared__ char smem[];
    int job = base_job + (int)blockIdx.z;
    int br  = (job == 1 || job == 3) ? 1 : 0;
    int mcnt = g_cnt[br];
    int m0 = blockIdx.y * CTA_M;
    if (m0 >= mcnt) return;
    int bx = blockIdx.x;
    int K  = c_jobK[job];
    int wioff = c_wioff[job];
    int tid = threadIdx.x;
    uint32_t sb = smem_u32(smem);

    float acc[2][8][4];
#pragma unroll
    for (int i = 0; i < 2; ++i)
#pragma unroll
        for (int j = 0; j < 8; ++j)
#pragma unroll
            for (int q = 0; q < 4; ++q) acc[i][j][q] = 0.f;

    const int nchunks = K / 32;          // 32 halves per chunk
    load_stage(sb, job, br, m0, bx, 0, K, wioff, tid);
    if (nchunks > 1) load_stage(sb + STAGE_B, job, br, m0, bx, 32, K, wioff, tid);
    if (nchunks > 2) load_stage(sb + 2 * STAGE_B, job, br, m0, bx, 64, K, wioff, tid);

    int wid = tid >> 5, lane = tid & 31;
    int wm = (wid & 3) * 32;
    int wn = (wid >> 2) * 64;
    uint32_t a_off  = (uint32_t)(wm + (lane & 15)) * ROWB + ((lane >> 4) << 4);
    uint32_t b_rowl = (lane & 7);
    uint32_t b_pair = (lane >> 4);
    uint32_t b_kh   = ((lane >> 3) & 1) * 16;

    for (int c = 0; c < nchunks; ++c) {
        int slot = c & (NSTAGE - 1);
        if (c > 0) __syncthreads();       // slot being overwritten was consumed
        int rem = nchunks - c;
        if (c + 3 < nchunks) {
            load_stage(sb + ((c + 3) & (NSTAGE - 1)) * STAGE_B,
                       job, br, m0, bx, (c + 3) * 32, K, wioff, tid);
            CP_WAIT3();
        } else if (rem == 3) {
            CP_WAIT2();
        } else if (rem == 2) {
            CP_WAIT1();
        } else {
            CP_WAIT0();
        }
        __syncthreads();                  // stage c visible to all warps
        uint32_t stu = sb + slot * STAGE_B;

#pragma unroll
        for (int s = 0; s < 2; ++s) {
            uint32_t ah[2][4];
#pragma unroll
            for (int tm = 0; tm < 2; ++tm)
                LDSM_X4(ah[tm], stu + a_off + tm * 16 * ROWB + s * 32);
            uint32_t bf[8][2];
#pragma unroll
            for (int tn = 0; tn < 8; tn += 2) {
                uint32_t row = wn + (tn + b_pair) * 8 + b_rowl;
                uint32_t addr = stu + PLANE_B + row * ROWB + s * 32 + b_kh;
                uint32_t r[4];
                LDSM_X4(r, addr);
                bf[tn][0] = r[0]; bf[tn][1] = r[1];
                bf[tn + 1][0] = r[2]; bf[tn + 1][1] = r[3];
            }
#pragma unroll
            for (int tm = 0; tm < 2; ++tm)
#pragma unroll
                for (int tn = 0; tn < 8; ++tn) MMA_F32ACC(acc[tm][tn], ah[tm], bf[tn]);
        }
    }

    // ---- epilogue: bias + tanh*sigmoid; layer1 -> fp16 h1; layer2 -> scatter fp32 ----
    const float* bh_p = (blockIdx.z == 0) ? bh_a : bh_b;
    const float* bg_p = (blockIdx.z == 0) ? bg_a : bg_b;
    int n_base = bx * 64 + (wid >> 2) * 32 + (lane & 3);
    int m_base = m0 + wm + (lane >> 2);
    __half* h1 = g_h1[br];

#pragma unroll
    for (int tn = 0; tn < 8; ++tn) {
        int n = n_base + tn * 4;
        float bhv = __ldg(bh_p + n);
        float bgv = __ldg(bg_p + n);
#pragma unroll
        for (int tm = 0; tm < 2; ++tm)
#pragma unroll
            for (int rr = 0; rr < 2; ++rr) {
                int m = m_base + tm * 16 + rr * 8;
                if (m < mcnt) {
                    float x = acc[tm][tn][rr * 2 + 0] + bhv;
                    float y = acc[tm][tn][rr * 2 + 1] + bgv;
                    float r = tanhf(x) * (1.0f / (1.0f + __expf(-y)));
                    if (job < 2) {
                        h1[(size_t)m * 512 + n] = __float2half_rn(r);
                    } else {
                        out[(size_t)g_idx[br][m] * 512 + n] = r;
                    }
                }
            }
    }
}

// ---- launch ----
extern "C" void kernel_launch(void* const* d_in, const int* in_sizes, int n_in,
                              void* d_out, int out_size) {
    const float* node_hidden     = (const float*)d_in[0];
    const float* node_context    = (const float*)d_in[1];
    const float* label_embedding = (const float*)d_in[2];
    const float* left_embedding  = (const float*)d_in[3];
    const int*   group           = (const int*)  d_in[4];
    const float* Wl1h = (const float*)d_in[5];
    const float* bl1h = (const float*)d_in[6];
    const float* Wl1g = (const float*)d_in[7];
    const float* bl1g = (const float*)d_in[8];
    const float* Wl2h = (const float*)d_in[9];
    const float* bl2h = (const float*)d_in[10];
    const float* Wl2g = (const float*)d_in[11];
    const float* bl2g = (const float*)d_in[12];
    const float* Wr1h = (const float*)d_in[13];
    const float* br1h = (const float*)d_in[14];
    const float* Wr1g = (const float*)d_in[15];
    const float* br1g = (const float*)d_in[16];
    const float* Wr2h = (const float*)d_in[17];
    const float* br2h = (const float*)d_in[18];
    const float* Wr2g = (const float*)d_in[19];
    const float* br2g = (const float*)d_in[20];
    (void)in_sizes; (void)n_in;

    float* out_children = (float*)d_out;
    float* out_mask     = (float*)d_out + (size_t)B_ * H_;
    int write_mask = (out_size >= (int)((size_t)B_ * H_ + B_)) ? 1 : 0;

    cudaFuncSetAttribute(gate_gemm_mma, cudaFuncAttributeMaxDynamicSharedMemorySize, SMEM_DYN);

    zero_cnt_kernel<<<1, 32>>>();
    prepack_w_kernel<<<dim3(48, 16, 4), dim3(32, 8)>>>(Wl1h, Wl1g, Wr1h, Wr1g,
                                                       Wl2h, Wl2g, Wr2h, Wr2g);
    prep_kernel<<<B_, 128>>>(node_hidden, node_context, label_embedding, left_embedding,
                             group, out_children, out_mask, write_mask);

    dim3 grid(H_ / 64, B_ / CTA_M, 2);   // idle M-blocks exit early
    gate_gemm_mma<<<grid, NTH, SMEM_DYN>>>(0, bl1h, bl1g, br1h, br1g, nullptr);
    gate_gemm_mma<<<grid, NTH, SMEM_DYN>>>(2, bl2h, bl2g, br2h, br2g, out_children);
}

// round 10
// speedup vs baseline: 7.0806x; 1.1571x over previous
#include <cuda_runtime.h>
#include <cuda_fp16.h>
#include <cstdint>
#include <math.h>

#define B_ 32768
#define H_ 512

#define CTA_M 128
#define NTH 256
#define ROWB 144                     // 128B data (64 halves) + 16B pad
#define PLANE_B (128 * ROWB)         // 18432
#define STAGE_B (2 * PLANE_B)        // 36864: A, W
#define NSTAGE 3
#define SMEM_DYN (NSTAGE * STAGE_B)  // 110592 -> 2 CTAs/SM (221KB of 228KB)

// ---- static device scratch ----
__device__ int g_cnt[2];
__device__ int g_idx[2][B_];
__device__ __align__(16) __half g_x1[2][(size_t)B_ * 1536];
__device__ __align__(16) __half g_le[(size_t)B_ * 512];
__device__ __align__(16) __half g_h1[2][(size_t)B_ * 512];
#define WI_TOTAL 4718592             // (1536+1536+512+1024)*1024
__device__ __align__(16) __half g_w[WI_TOTAL];

__constant__ int c_jobK[4]  = {1536, 1536, 512, 1024};
__constant__ int c_wioff[4] = {0, 1572864, 3145728, 3670016};

// ---- PTX helpers (baseline ISA only; no arch-'a' features) ----
__device__ __forceinline__ uint32_t smem_u32(const void* p) {
    uint32_t a;
    asm("{ .reg .u64 t; cvta.to.shared.u64 t, %1; cvt.u32.u64 %0, t; }" : "=r"(a) : "l"(p));
    return a;
}
#define CP_ASYNC16(d, s) asm volatile("cp.async.cg.shared.global [%0], [%1], 16;" :: "r"(d), "l"(s))
#define CP_COMMIT()      asm volatile("cp.async.commit_group;" ::: "memory")
#define CP_WAIT1()       asm volatile("cp.async.wait_group 1;" ::: "memory")
#define CP_WAIT0()       asm volatile("cp.async.wait_group 0;" ::: "memory")
#define LDSM_X4(r, addr) \
    asm volatile("ldmatrix.sync.aligned.m8n8.x4.shared.b16 {%0,%1,%2,%3}, [%4];" \
        : "=r"((r)[0]), "=r"((r)[1]), "=r"((r)[2]), "=r"((r)[3]) : "r"(addr))
#define MMA_F32ACC(c, a, b) \
    asm volatile("mma.sync.aligned.m16n8k16.row.col.f32.f16.f16.f32 " \
        "{%0,%1,%2,%3}, {%4,%5,%6,%7}, {%8,%9}, {%0,%1,%2,%3};" \
        : "+f"((c)[0]), "+f"((c)[1]), "+f"((c)[2]), "+f"((c)[3]) \
        : "r"((a)[0]), "r"((a)[1]), "r"((a)[2]), "r"((a)[3]), "r"((b)[0]), "r"((b)[1]))

// ---- small kernels ----
__global__ void zero_cnt_kernel() { if (threadIdx.x < 2) g_cnt[threadIdx.x] = 0; }

// fused prep: classify row, build compact index, gather+convert activations,
// zero g==2 output rows, write mask. One block per source row.
__global__ void prep_kernel(const float* __restrict__ nh, const float* __restrict__ nc,
                            const float* __restrict__ lab, const float* __restrict__ le,
                            const int* __restrict__ group,
                            float* __restrict__ out_children,
                            float* __restrict__ mask_out, int write_mask) {
    int row = blockIdx.x;
    int tid = threadIdx.x;               // 128 threads
    int g = __ldg(group + row);
    __shared__ int s_p;
    if (tid == 0) {
        if (write_mask) mask_out[row] = (g == 2) ? 1.0f : 0.0f;
        if (g < 2) {
            int p = atomicAdd(&g_cnt[g], 1);
            g_idx[g][p] = row;
            s_p = p;
        }
    }
    __syncthreads();
    if (g == 2) {
        float4 z = make_float4(0.f, 0.f, 0.f, 0.f);
        reinterpret_cast<float4*>(out_children + (size_t)row * H_)[tid] = z;
        return;
    }
    int p = s_p;
    __half* x = g_x1[g];
#pragma unroll
    for (int i = 0; i < 3; ++i) {
        int c4 = tid + i * 128;
        const float* srcp = (c4 < 128) ? nh : (c4 < 256) ? nc : lab;
        int loc = (c4 & 127) * 4;
        float4 v = *reinterpret_cast<const float4*>(srcp + (size_t)row * 512 + loc);
        __half h[4];
        h[0] = __float2half_rn(v.x); h[1] = __float2half_rn(v.y);
        h[2] = __float2half_rn(v.z); h[3] = __float2half_rn(v.w);
        *reinterpret_cast<uint2*>(x + (size_t)p * 1536 + c4 * 4) = *reinterpret_cast<uint2*>(h);
    }
    if (g == 1) {
        float4 v = *reinterpret_cast<const float4*>(le + (size_t)row * 512 + tid * 4);
        __half h[4];
        h[0] = __float2half_rn(v.x); h[1] = __float2half_rn(v.y);
        h[2] = __float2half_rn(v.z); h[3] = __float2half_rn(v.w);
        *reinterpret_cast<uint2*>(g_le + (size_t)p * 512 + tid * 4) = *reinterpret_cast<uint2*>(h);
    }
}

// weight prepack: [K,512] Wh,Wg -> interleaved transposed rows [2n+p][K], fp16
__global__ void prepack_w_kernel(const float* w0h, const float* w0g,
                                 const float* w1h, const float* w1g,
                                 const float* w2h, const float* w2g,
                                 const float* w3h, const float* w3g) {
    int j = blockIdx.z;
    const float* Wh = (j == 0) ? w0h : (j == 1) ? w1h : (j == 2) ? w2h : w3h;
    const float* Wg = (j == 0) ? w0g : (j == 1) ? w1g : (j == 2) ? w2g : w3g;
    int K = c_jobK[j];
    int k0 = blockIdx.x * 32;
    if (k0 >= K) return;
    int n0 = blockIdx.y * 32;
    __shared__ float sh[32][33], sg[32][33];
    int tx = threadIdx.x, ty = threadIdx.y;
#pragma unroll
    for (int i = 0; i < 4; ++i) {
        sh[ty + 8 * i][tx] = Wh[(size_t)(k0 + ty + 8 * i) * 512 + n0 + tx];
        sg[ty + 8 * i][tx] = Wg[(size_t)(k0 + ty + 8 * i) * 512 + n0 + tx];
    }
    __syncthreads();
    size_t base = (size_t)c_wioff[j];
#pragma unroll
    for (int i = 0; i < 4; ++i) {
        int n = n0 + ty + 8 * i;
        int k = k0 + tx;
        g_w[base + (size_t)(2 * n) * K + k]     = __float2half_rn(sh[tx][ty + 8 * i]);
        g_w[base + (size_t)(2 * n + 1) * K + k] = __float2half_rn(sg[tx][ty + 8 * i]);
    }
}

// ---- stage loader: A + W planes, 128 rows x 128B each ----
__device__ __forceinline__ void load_stage(uint32_t stu, int job, int br, int m0,
                                           int bx, int k0, int K, int wioff, int tid) {
    const __half* a;
    int astr, acol;
    if (job <= 1)      { a = g_x1[br]; astr = 1536; acol = k0; }
    else if (job == 2) { a = g_h1[0];  astr = 512;  acol = k0; }
    else {
        if (k0 < 512)  { a = g_h1[1];  astr = 512;  acol = k0; }
        else           { a = g_le;     astr = 512;  acol = k0 - 512; }
    }
#pragma unroll
    for (int i = 0; i < 4; ++i) {
        int idx = tid + i * NTH;           // 0..1023
        int row = idx >> 3;                // 0..127
        int q   = idx & 7;                 // 16B chunk = 8 halves
        uint32_t d = stu + row * ROWB + q * 16;
        CP_ASYNC16(d, a + (size_t)(m0 + row) * astr + acol + q * 8);
        int grow = bx * 128 + row;
        CP_ASYNC16(d + PLANE_B, g_w + wioff + (size_t)grow * K + k0 + q * 8);
    }
    CP_COMMIT();
}

// ---- fused gated GEMM: single-pass fp16, f32 accumulators ----
// BK=64 chunks, 3-stage pipeline, ONE barrier per chunk, warp-staggered s order.
__global__ void __launch_bounds__(NTH, 2)
gate_gemm_mma(int base_job,
              const float* __restrict__ bh_a, const float* __restrict__ bg_a,
              const float* __restrict__ bh_b, const float* __restrict__ bg_b,
              float* __restrict__ out) {
    extern __shared__ char smem[];
    int job = base_job + (int)blockIdx.z;
    int br  = (job == 1 || job == 3) ? 1 : 0;
    int mcnt = g_cnt[br];
    int m0 = blockIdx.y * CTA_M;
    if (m0 >= mcnt) return;
    int bx = blockIdx.x;
    int K  = c_jobK[job];
    int wioff = c_wioff[job];
    int tid = threadIdx.x;
    uint32_t sb = smem_u32(smem);

    float acc[2][8][4];
#pragma unroll
    for (int i = 0; i < 2; ++i)
#pragma unroll
        for (int j = 0; j < 8; ++j)
#pragma unroll
            for (int q = 0; q < 4; ++q) acc[i][j][q] = 0.f;

    const int nchunks = K / 64;          // 64 halves (128B) per chunk
    load_stage(sb, job, br, m0, bx, 0, K, wioff, tid);

    int wid = tid >> 5, lane = tid & 31;
    int wm = (wid & 3) * 32;
    int wn = (wid >> 2) * 64;
    int s0 = wid & 3;                    // stagger: each warp starts at a different s-block
    uint32_t a_off  = (uint32_t)(wm + (lane & 15)) * ROWB + ((lane >> 4) << 4);
    uint32_t b_rowl = (lane & 7);
    uint32_t b_pair = (lane >> 4);
    uint32_t b_kh   = ((lane >> 3) & 1) * 16;

    int slot = 0;
    for (int c = 0; c < nchunks; ++c) {
        int nslot = (slot + 1 == NSTAGE) ? 0 : slot + 1;
        // issue prefetch for chunk c+1 (slot proven free: slowest warp reads (c+2)%3)
        if (c + 1 < nchunks) {
            load_stage(sb + nslot * STAGE_B, job, br, m0, bx, (c + 1) * 64, K, wioff, tid);
            CP_WAIT1();                   // my chunk-c copies complete
        } else {
            CP_WAIT0();
        }
        __syncthreads();                  // everyone's chunk-c copies visible
        uint32_t stu = sb + slot * STAGE_B;
        slot = nslot;

#pragma unroll
        for (int si = 0; si < 4; ++si) {
            int s = (si + s0) & 3;        // warp-dependent order, all data resident
            uint32_t koff = (uint32_t)s * 32;
            uint32_t ah[2][4];
#pragma unroll
            for (int tm = 0; tm < 2; ++tm)
                LDSM_X4(ah[tm], stu + a_off + tm * 16 * ROWB + koff);
            uint32_t bf[8][2];
#pragma unroll
            for (int tn = 0; tn < 8; tn += 2) {
                uint32_t row = wn + (tn + b_pair) * 8 + b_rowl;
                uint32_t addr = stu + PLANE_B + row * ROWB + koff + b_kh;
                uint32_t r[4];
                LDSM_X4(r, addr);
                bf[tn][0] = r[0]; bf[tn][1] = r[1];
                bf[tn + 1][0] = r[2]; bf[tn + 1][1] = r[3];
            }
#pragma unroll
            for (int tm = 0; tm < 2; ++tm)
#pragma unroll
                for (int tn = 0; tn < 8; ++tn) MMA_F32ACC(acc[tm][tn], ah[tm], bf[tn]);
        }
    }

    // ---- epilogue: bias + tanh*sigmoid; layer1 -> fp16 h1; layer2 -> scatter fp32 ----
    const float* bh_p = (blockIdx.z == 0) ? bh_a : bh_b;
    const float* bg_p = (blockIdx.z == 0) ? bg_a : bg_b;
    int n_base = bx * 64 + (wid >> 2) * 32 + (lane & 3);
    int m_base = m0 + wm + (lane >> 2);
    __half* h1 = g_h1[br];

#pragma unroll
    for (int tn = 0; tn < 8; ++tn) {
        int n = n_base + tn * 4;
        float bhv = __ldg(bh_p + n);
        float bgv = __ldg(bg_p + n);
#pragma unroll
        for (int tm = 0; tm < 2; ++tm)
#pragma unroll
            for (int rr = 0; rr < 2; ++rr) {
                int m = m_base + tm * 16 + rr * 8;
                if (m < mcnt) {
                    float x = acc[tm][tn][rr * 2 + 0] + bhv;
                    float y = acc[tm][tn][rr * 2 + 1] + bgv;
                    float r = tanhf(x) * (1.0f / (1.0f + __expf(-y)));
                    if (job < 2) {
                        h1[(size_t)m * 512 + n] = __float2half_rn(r);
                    } else {
                        out[(size_t)g_idx[br][m] * 512 + n] = r;
                    }
                }
            }
    }
}

// ---- launch ----
extern "C" void kernel_launch(void* const* d_in, const int* in_sizes, int n_in,
                              void* d_out, int out_size) {
    const float* node_hidden     = (const float*)d_in[0];
    const float* node_context    = (const float*)d_in[1];
    const float* label_embedding = (const float*)d_in[2];
    const float* left_embedding  = (const float*)d_in[3];
    const int*   group           = (const int*)  d_in[4];
    const float* Wl1h = (const float*)d_in[5];
    const float* bl1h = (const float*)d_in[6];
    const float* Wl1g = (const float*)d_in[7];
    const float* bl1g = (const float*)d_in[8];
    const float* Wl2h = (const float*)d_in[9];
    const float* bl2h = (const float*)d_in[10];
    const float* Wl2g = (const float*)d_in[11];
    const float* bl2g = (const float*)d_in[12];
    const float* Wr1h = (const float*)d_in[13];
    const float* br1h = (const float*)d_in[14];
    const float* Wr1g = (const float*)d_in[15];
    const float* br1g = (const float*)d_in[16];
    const float* Wr2h = (const float*)d_in[17];
    const float* br2h = (const float*)d_in[18];
    const float* Wr2g = (const float*)d_in[19];
    const float* br2g = (const float*)d_in[20];
    (void)in_sizes; (void)n_in;

    float* out_children = (float*)d_out;
    float* out_mask     = (float*)d_out + (size_t)B_ * H_;
    int write_mask = (out_size >= (int)((size_t)B_ * H_ + B_)) ? 1 : 0;

    cudaFuncSetAttribute(gate_gemm_mma, cudaFuncAttributeMaxDynamicSharedMemorySize, SMEM_DYN);

    zero_cnt_kernel<<<1, 32>>>();
    prepack_w_kernel<<<dim3(48, 16, 4), dim3(32, 8)>>>(Wl1h, Wl1g, Wr1h, Wr1g,
                                                       Wl2h, Wl2g, Wr2h, Wr2g);
    prep_kernel<<<B_, 128>>>(node_hidden, node_context, label_embedding, left_embedding,
                             group, out_children, out_mask, write_mask);

    dim3 grid(H_ / 64, B_ / CTA_M, 2);   // idle M-blocks exit early
    gate_gemm_mma<<<grid, NTH, SMEM_DYN>>>(0, bl1h, bl1g, br1h, br1g, nullptr);
    gate_gemm_mma<<<grid, NTH, SMEM_DYN>>>(2, bl2h, bl2g, br2h, br2g, out_children);
}